// round 1
// baseline (speedup 1.0000x reference)
#include <cuda_runtime.h>
#include <cuda_bf16.h>
#include <math.h>

// ---------------------------------------------------------------------------
// WaveletSwinTransformerBlock — fp32 baseline
// B=8, H=W=128, Cw=Cs=64, dim=256, nH=8, hd=32, WS=8, hid=1024
// ---------------------------------------------------------------------------

#define B_     8
#define H_     128
#define W_     128
#define HW_    (H_*W_)           // 16384
#define P_TOT  (B_*HW_)          // 131072
#define CDIM   256
#define NHEAD  8
#define HD     32
#define HID    1024

// ------------------------- scratch buffers (static) ------------------------
__device__ float g_inx[(size_t)P_TOT*128];   // packed concat(LH,HL)
__device__ float g_iny[(size_t)P_TOT*64];    // packed Spat
__device__ float g_inz[(size_t)P_TOT*64];    // packed HH
__device__ float g_x    [(size_t)P_TOT*CDIM];
__device__ float g_y    [(size_t)P_TOT*CDIM];
__device__ float g_xn   [(size_t)P_TOT*CDIM];  // window layout
__device__ float g_yn   [(size_t)P_TOT*CDIM];  // window layout
__device__ float g_short[(size_t)P_TOT*CDIM];  // pixel layout
__device__ float g_q    [(size_t)P_TOT*CDIM];
__device__ float g_k    [(size_t)P_TOT*CDIM];
__device__ float g_v    [(size_t)P_TOT*CDIM];
__device__ float g_ao   [(size_t)P_TOT*CDIM];  // attention out (window layout)
__device__ float g_po   [(size_t)P_TOT*CDIM];  // proj out (window layout)
__device__ float g_zt   [(size_t)P_TOT*CDIM];  // pixel layout
__device__ float g_ln2  [(size_t)P_TOT*CDIM];
__device__ float g_h    [(size_t)P_TOT*HID];
__device__ float g_zt2  [(size_t)P_TOT*CDIM];

// pixel index -> window-layout row index
__device__ __forceinline__ int win_row(int p) {
    int b  = p >> 14;          // / 16384
    int hw = p & 16383;
    int h  = hw >> 7, w = hw & 127;
    int win = (b << 8) | ((h >> 3) << 4) | (w >> 3);
    int tok = ((h & 7) << 3) | (w & 7);
    return (win << 6) | tok;
}

// ------------------------- pack: NCHW -> [P, Cin] row-major ----------------
// src [B][Cin][HW] ; dst[(b*HW+hw)*rowStride + colOff + c] = src[(b*Cin+c)*HW+hw]
__global__ void pack_kernel(const float* __restrict__ src, float* __restrict__ dst,
                            int Cin, int rowStride, int colOff)
{
    __shared__ float s[32][33];
    int hw0 = blockIdx.x * 32;
    int c0  = blockIdx.y * 32;
    int b   = blockIdx.z;
    int tx = threadIdx.x, ty = threadIdx.y;   // (32, 8)
#pragma unroll
    for (int i = 0; i < 4; i++)
        s[ty + 8*i][tx] = src[((size_t)(b*Cin + c0 + ty + 8*i))*HW_ + hw0 + tx];
    __syncthreads();
#pragma unroll
    for (int i = 0; i < 4; i++)
        dst[(size_t)(b*HW_ + hw0 + ty + 8*i)*rowStride + colOff + c0 + tx] = s[tx][ty + 8*i];
}

// ------------------------- unpack: [P, C] -> NCHW --------------------------
__global__ void unpack_kernel(const float* __restrict__ src, float* __restrict__ dst)
{
    __shared__ float s[32][33];
    int hw0 = blockIdx.x * 32;
    int c0  = blockIdx.y * 32;
    int b   = blockIdx.z;
    int tx = threadIdx.x, ty = threadIdx.y;
#pragma unroll
    for (int i = 0; i < 4; i++)
        s[ty + 8*i][tx] = src[(size_t)(b*HW_ + hw0 + ty + 8*i)*CDIM + c0 + tx];
    __syncthreads();
#pragma unroll
    for (int i = 0; i < 4; i++)
        dst[(size_t)(b*CDIM + c0 + ty + 8*i)*HW_ + hw0 + tx] = s[tx][ty + 8*i];
}

// ------------------------- generic GEMM: C = (A @ W^T + bias)*alpha --------
// A [M,K] row-major, W [N,K] row-major, optional gelu, optional residual add.
#define BM 64
#define BN 64
#define BK 16

__global__ __launch_bounds__(256)
void gemm_tn(const float* __restrict__ A, const float* __restrict__ Wm,
             const float* __restrict__ bias, const float* __restrict__ res,
             float* __restrict__ C, int M, int N, int K, float alpha, int gelu)
{
    __shared__ __align__(16) float As[BK][BM + 4];
    __shared__ __align__(16) float Ws[BK][BN + 4];
    int bx = blockIdx.x, by = blockIdx.y;
    int tid = threadIdx.x;
    int tx = tid & 15, ty = tid >> 4;       // 16x16
    const float* Ap = A  + (size_t)by * BM * K;
    const float* Wp = Wm + (size_t)bx * BN * K;
    float acc[4][4] = {};

    int lk = tid & 15;      // k within tile
    int lr = tid >> 4;      // base row

    for (int k0 = 0; k0 < K; k0 += BK) {
#pragma unroll
        for (int i = 0; i < 4; i++) {
            As[lk][lr + 16*i] = Ap[(size_t)(lr + 16*i)*K + k0 + lk];
            Ws[lk][lr + 16*i] = Wp[(size_t)(lr + 16*i)*K + k0 + lk];
        }
        __syncthreads();
#pragma unroll
        for (int kk = 0; kk < BK; kk++) {
            float4 a4 = *(const float4*)&As[kk][ty*4];
            float4 b4 = *(const float4*)&Ws[kk][tx*4];
            float av[4] = {a4.x, a4.y, a4.z, a4.w};
            float bv[4] = {b4.x, b4.y, b4.z, b4.w};
#pragma unroll
            for (int i = 0; i < 4; i++)
#pragma unroll
                for (int j = 0; j < 4; j++)
                    acc[i][j] = fmaf(av[i], bv[j], acc[i][j]);
        }
        __syncthreads();
    }

#pragma unroll
    for (int i = 0; i < 4; i++) {
        int row = by*BM + ty*4 + i;
#pragma unroll
        for (int j = 0; j < 4; j++) {
            int col = bx*BN + tx*4 + j;
            float v = (acc[i][j] + bias[col]) * alpha;
            if (gelu) v = 0.5f * v * (1.0f + erff(v * 0.70710678118654752f));
            if (res)  v += res[(size_t)row*N + col];
            C[(size_t)row*N + col] = v;
        }
    }
}

// ------------------------- LayerNorm + window partition --------------------
// warp per pixel; in: pixel-layout rows; out: window-layout rows (if to_window)
__global__ void ln_part_kernel(const float* __restrict__ x, const float* __restrict__ g,
                               const float* __restrict__ b, float* __restrict__ out,
                               int to_window)
{
    int warp = threadIdx.x >> 5, lane = threadIdx.x & 31;
    int p = blockIdx.x * 8 + warp;
    const float* row = x + (size_t)p * CDIM;
    float4 v0 = *(const float4*)(row + lane*4);
    float4 v1 = *(const float4*)(row + 128 + lane*4);
    float s  = v0.x+v0.y+v0.z+v0.w + v1.x+v1.y+v1.z+v1.w;
    float sq = v0.x*v0.x+v0.y*v0.y+v0.z*v0.z+v0.w*v0.w
             + v1.x*v1.x+v1.y*v1.y+v1.z*v1.z+v1.w*v1.w;
#pragma unroll
    for (int o = 16; o; o >>= 1) {
        s  += __shfl_xor_sync(0xffffffffu, s,  o);
        sq += __shfl_xor_sync(0xffffffffu, sq, o);
    }
    float mean = s * (1.0f/CDIM);
    float var  = sq * (1.0f/CDIM) - mean*mean;
    float rstd = rsqrtf(var + 1e-5f);
    int r = to_window ? win_row(p) : p;
    float* orow = out + (size_t)r * CDIM;
    int c0 = lane*4;
    float4 o0, o1;
    o0.x = (v0.x-mean)*rstd*g[c0+0] + b[c0+0];
    o0.y = (v0.y-mean)*rstd*g[c0+1] + b[c0+1];
    o0.z = (v0.z-mean)*rstd*g[c0+2] + b[c0+2];
    o0.w = (v0.w-mean)*rstd*g[c0+3] + b[c0+3];
    o1.x = (v1.x-mean)*rstd*g[c0+128+0] + b[c0+128+0];
    o1.y = (v1.y-mean)*rstd*g[c0+128+1] + b[c0+128+1];
    o1.z = (v1.z-mean)*rstd*g[c0+128+2] + b[c0+128+2];
    o1.w = (v1.w-mean)*rstd*g[c0+128+3] + b[c0+128+3];
    *(float4*)(orow + c0)       = o0;
    *(float4*)(orow + 128 + c0) = o1;
}

// ------------------------- residual + LN2 (window-reverse) -----------------
// zt[p] = shortcut[p] + proj[win_row(p)];  ln2 = LN(zt)
__global__ void res_ln2_kernel(const float* __restrict__ proj, const float* __restrict__ sc,
                               const float* __restrict__ g, const float* __restrict__ b,
                               float* __restrict__ zt, float* __restrict__ ln2)
{
    int warp = threadIdx.x >> 5, lane = threadIdx.x & 31;
    int p = blockIdx.x * 8 + warp;
    int r = win_row(p);
    const float* prow = proj + (size_t)r * CDIM;
    const float* srow = sc   + (size_t)p * CDIM;
    int c0 = lane*4;
    float4 a0 = *(const float4*)(prow + c0);
    float4 a1 = *(const float4*)(prow + 128 + c0);
    float4 s0 = *(const float4*)(srow + c0);
    float4 s1 = *(const float4*)(srow + 128 + c0);
    float4 v0 = {a0.x+s0.x, a0.y+s0.y, a0.z+s0.z, a0.w+s0.w};
    float4 v1 = {a1.x+s1.x, a1.y+s1.y, a1.z+s1.z, a1.w+s1.w};
    *(float4*)(zt + (size_t)p*CDIM + c0)       = v0;
    *(float4*)(zt + (size_t)p*CDIM + 128 + c0) = v1;
    float s  = v0.x+v0.y+v0.z+v0.w + v1.x+v1.y+v1.z+v1.w;
    float sq = v0.x*v0.x+v0.y*v0.y+v0.z*v0.z+v0.w*v0.w
             + v1.x*v1.x+v1.y*v1.y+v1.z*v1.z+v1.w*v1.w;
#pragma unroll
    for (int o = 16; o; o >>= 1) {
        s  += __shfl_xor_sync(0xffffffffu, s,  o);
        sq += __shfl_xor_sync(0xffffffffu, sq, o);
    }
    float mean = s * (1.0f/CDIM);
    float var  = sq * (1.0f/CDIM) - mean*mean;
    float rstd = rsqrtf(var + 1e-5f);
    float* orow = ln2 + (size_t)p * CDIM;
    float4 o0, o1;
    o0.x=(v0.x-mean)*rstd*g[c0+0]+b[c0+0];  o0.y=(v0.y-mean)*rstd*g[c0+1]+b[c0+1];
    o0.z=(v0.z-mean)*rstd*g[c0+2]+b[c0+2];  o0.w=(v0.w-mean)*rstd*g[c0+3]+b[c0+3];
    o1.x=(v1.x-mean)*rstd*g[c0+128+0]+b[c0+128+0];  o1.y=(v1.y-mean)*rstd*g[c0+128+1]+b[c0+128+1];
    o1.z=(v1.z-mean)*rstd*g[c0+128+2]+b[c0+128+2];  o1.w=(v1.w-mean)*rstd*g[c0+128+3]+b[c0+128+3];
    *(float4*)(orow + c0)       = o0;
    *(float4*)(orow + 128 + c0) = o1;
}

// ------------------------- windowed attention ------------------------------
// one block per (window, head); q is pre-scaled by hd^-0.5 (GEMM epilogue)
__global__ __launch_bounds__(128)
void attn_kernel(const float* __restrict__ q, const float* __restrict__ k,
                 const float* __restrict__ v, const float* __restrict__ rpb,
                 float* __restrict__ out)
{
    __shared__ float qs[64][33];
    __shared__ float ks[64][33];
    __shared__ float vs[64][33];
    __shared__ float S [64][65];
    int win = blockIdx.x, h = blockIdx.y;
    int tid = threadIdx.x;
    size_t base = ((size_t)win * 64) * CDIM + h * HD;

    for (int idx = tid; idx < 64*HD; idx += 128) {
        int n = idx >> 5, d = idx & 31;
        qs[n][d] = q[base + (size_t)n*CDIM + d];
        ks[n][d] = k[base + (size_t)n*CDIM + d];
        vs[n][d] = v[base + (size_t)n*CDIM + d];
    }
    __syncthreads();

    for (int idx = tid; idx < 64*64; idx += 128) {
        int n = idx >> 6, m = idx & 63;
        float s = 0.f;
#pragma unroll
        for (int d = 0; d < HD; d++) s = fmaf(qs[n][d], ks[m][d], s);
        int di = (n >> 3) - (m >> 3) + 7;
        int dj = (n & 7)  - (m & 7)  + 7;
        s += rpb[(di*15 + dj)*NHEAD + h];
        S[n][m] = s;
    }
    __syncthreads();

    if (tid < 64) {
        int n = tid;
        float mx = -1e30f;
#pragma unroll
        for (int m = 0; m < 64; m++) mx = fmaxf(mx, S[n][m]);
        float sum = 0.f;
#pragma unroll
        for (int m = 0; m < 64; m++) { float e = expf(S[n][m] - mx); S[n][m] = e; sum += e; }
        float inv = 1.0f / sum;
#pragma unroll
        for (int m = 0; m < 64; m++) S[n][m] *= inv;
    }
    __syncthreads();

    for (int idx = tid; idx < 64*HD; idx += 128) {
        int n = idx >> 5, d = idx & 31;
        float o = 0.f;
#pragma unroll
        for (int m = 0; m < 64; m++) o = fmaf(S[n][m], vs[m][d], o);
        out[base + (size_t)n*CDIM + d] = o;
    }
}

// ---------------------------------------------------------------------------
extern "C" void kernel_launch(void* const* d_in, const int* in_sizes, int n_in,
                              void* d_out, int out_size)
{
    const float* LH      = (const float*)d_in[0];
    const float* HL      = (const float*)d_in[1];
    const float* HH      = (const float*)d_in[2];
    const float* Spat    = (const float*)d_in[3];
    const float* w_hllh  = (const float*)d_in[4];
    const float* b_hllh  = (const float*)d_in[5];
    const float* w_hh    = (const float*)d_in[6];
    const float* b_hh    = (const float*)d_in[7];
    const float* w_spat  = (const float*)d_in[8];
    const float* b_spat  = (const float*)d_in[9];
    const float* ln1x_g  = (const float*)d_in[10];
    const float* ln1x_b  = (const float*)d_in[11];
    const float* ln1y_g  = (const float*)d_in[12];
    const float* ln1y_b  = (const float*)d_in[13];
    const float* qkv_w   = (const float*)d_in[14];
    const float* qkv_b   = (const float*)d_in[15];
    const float* qkv2_w  = (const float*)d_in[16];
    const float* qkv2_b  = (const float*)d_in[17];
    const float* qkv3_w  = (const float*)d_in[18];
    const float* qkv3_b  = (const float*)d_in[19];
    const float* proj_w  = (const float*)d_in[20];
    const float* proj_b  = (const float*)d_in[21];
    const float* rpb     = (const float*)d_in[22];
    const float* ln2_g   = (const float*)d_in[23];
    const float* ln2_b   = (const float*)d_in[24];
    const float* fc1_w   = (const float*)d_in[25];
    const float* fc1_b   = (const float*)d_in[26];
    const float* fc2_w   = (const float*)d_in[27];
    const float* fc2_b   = (const float*)d_in[28];
    float* out = (float*)d_out;

    float *inx, *iny, *inz, *x, *y, *xn, *yn, *shrt, *q, *k, *v, *ao, *po, *zt, *ln2, *hbuf, *zt2;
    cudaGetSymbolAddress((void**)&inx,  g_inx);
    cudaGetSymbolAddress((void**)&iny,  g_iny);
    cudaGetSymbolAddress((void**)&inz,  g_inz);
    cudaGetSymbolAddress((void**)&x,    g_x);
    cudaGetSymbolAddress((void**)&y,    g_y);
    cudaGetSymbolAddress((void**)&xn,   g_xn);
    cudaGetSymbolAddress((void**)&yn,   g_yn);
    cudaGetSymbolAddress((void**)&shrt, g_short);
    cudaGetSymbolAddress((void**)&q,    g_q);
    cudaGetSymbolAddress((void**)&k,    g_k);
    cudaGetSymbolAddress((void**)&v,    g_v);
    cudaGetSymbolAddress((void**)&ao,   g_ao);
    cudaGetSymbolAddress((void**)&po,   g_po);
    cudaGetSymbolAddress((void**)&zt,   g_zt);
    cudaGetSymbolAddress((void**)&ln2,  g_ln2);
    cudaGetSymbolAddress((void**)&hbuf, g_h);
    cudaGetSymbolAddress((void**)&zt2,  g_zt2);

    dim3 tb(32, 8);
    const int M = P_TOT;
    const float qscale = 0.17677669529663688f;   // 32^-0.5

    // pack NCHW -> row-major
    pack_kernel<<<dim3(HW_/32, 2, B_), tb>>>(LH,   inx, 64, 128, 0);
    pack_kernel<<<dim3(HW_/32, 2, B_), tb>>>(HL,   inx, 64, 128, 64);
    pack_kernel<<<dim3(HW_/32, 2, B_), tb>>>(HH,   inz, 64, 64, 0);
    pack_kernel<<<dim3(HW_/32, 2, B_), tb>>>(Spat, iny, 64, 64, 0);

    // 1x1 convs
    gemm_tn<<<dim3(4, M/64), 256>>>(inx, w_hllh, b_hllh, nullptr, x,    M, 256, 128, 1.f, 0);
    gemm_tn<<<dim3(4, M/64), 256>>>(inz, w_hh,   b_hh,   nullptr, shrt, M, 256, 64,  1.f, 0);
    gemm_tn<<<dim3(4, M/64), 256>>>(iny, w_spat, b_spat, nullptr, y,    M, 256, 64,  1.f, 0);

    // LN + window partition
    ln_part_kernel<<<M/8, 256>>>(x, ln1x_g, ln1x_b, xn, 1);
    ln_part_kernel<<<M/8, 256>>>(y, ln1y_g, ln1y_b, yn, 1);

    // q/k/v projections (q scaled by hd^-0.5)
    gemm_tn<<<dim3(4, M/64), 256>>>(xn, qkv_w,  qkv_b,  nullptr, q, M, 256, 256, qscale, 0);
    gemm_tn<<<dim3(4, M/64), 256>>>(yn, qkv2_w, qkv2_b, nullptr, k, M, 256, 256, 1.f, 0);
    gemm_tn<<<dim3(4, M/64), 256>>>(yn, qkv3_w, qkv3_b, nullptr, v, M, 256, 256, 1.f, 0);

    // windowed attention
    attn_kernel<<<dim3(2048, NHEAD), 128>>>(q, k, v, rpb, ao);

    // output projection
    gemm_tn<<<dim3(4, M/64), 256>>>(ao, proj_w, proj_b, nullptr, po, M, 256, 256, 1.f, 0);

    // window reverse + residual + LN2
    res_ln2_kernel<<<M/8, 256>>>(po, shrt, ln2_g, ln2_b, zt, ln2);

    // MLP
    gemm_tn<<<dim3(16, M/64), 256>>>(ln2,  fc1_w, fc1_b, nullptr, hbuf, M, HID, 256, 1.f, 1);
    gemm_tn<<<dim3(4,  M/64), 256>>>(hbuf, fc2_w, fc2_b, zt,      zt2,  M, 256, HID, 1.f, 0);

    // [P,C] -> NCHW
    unpack_kernel<<<dim3(HW_/32, 8, B_), tb>>>(zt2, out);
}

// round 2
// speedup vs baseline: 2.3841x; 2.3841x over previous
#include <cuda_runtime.h>
#include <cuda_bf16.h>
#include <math.h>
#include <stdint.h>

// ---------------------------------------------------------------------------
// WaveletSwinTransformerBlock — tf32 tensor-core GEMMs (mma.sync m16n8k8)
// B=8, H=W=128, Cw=Cs=64, dim=256, nH=8, hd=32, WS=8, hid=1024
// ---------------------------------------------------------------------------

#define B_     8
#define H_     128
#define W_     128
#define HW_    (H_*W_)           // 16384
#define P_TOT  (B_*HW_)          // 131072
#define CDIM   256
#define NHEAD  8
#define HD     32
#define HID    1024

// ------------------------- scratch buffers (static) ------------------------
__device__ float g_inx[(size_t)P_TOT*128];
__device__ float g_iny[(size_t)P_TOT*64];
__device__ float g_inz[(size_t)P_TOT*64];
__device__ float g_x    [(size_t)P_TOT*CDIM];
__device__ float g_y    [(size_t)P_TOT*CDIM];
__device__ float g_xn   [(size_t)P_TOT*CDIM];
__device__ float g_yn   [(size_t)P_TOT*CDIM];
__device__ float g_short[(size_t)P_TOT*CDIM];
__device__ float g_q    [(size_t)P_TOT*CDIM];
__device__ float g_k    [(size_t)P_TOT*CDIM];
__device__ float g_v    [(size_t)P_TOT*CDIM];
__device__ float g_ao   [(size_t)P_TOT*CDIM];
__device__ float g_po   [(size_t)P_TOT*CDIM];
__device__ float g_zt   [(size_t)P_TOT*CDIM];
__device__ float g_ln2  [(size_t)P_TOT*CDIM];
__device__ float g_h    [(size_t)P_TOT*HID];
__device__ float g_zt2  [(size_t)P_TOT*CDIM];

__device__ __forceinline__ int win_row(int p) {
    int b  = p >> 14;
    int hw = p & 16383;
    int h  = hw >> 7, w = hw & 127;
    int win = (b << 8) | ((h >> 3) << 4) | (w >> 3);
    int tok = ((h & 7) << 3) | (w & 7);
    return (win << 6) | tok;
}

// ------------------------- pack: NCHW -> [P, Cin] row-major ----------------
__global__ void pack_kernel(const float* __restrict__ src, float* __restrict__ dst,
                            int Cin, int rowStride, int colOff)
{
    __shared__ float s[32][33];
    int hw0 = blockIdx.x * 32;
    int c0  = blockIdx.y * 32;
    int b   = blockIdx.z;
    int tx = threadIdx.x, ty = threadIdx.y;
#pragma unroll
    for (int i = 0; i < 4; i++)
        s[ty + 8*i][tx] = src[((size_t)(b*Cin + c0 + ty + 8*i))*HW_ + hw0 + tx];
    __syncthreads();
#pragma unroll
    for (int i = 0; i < 4; i++)
        dst[(size_t)(b*HW_ + hw0 + ty + 8*i)*rowStride + colOff + c0 + tx] = s[tx][ty + 8*i];
}

// ------------------------- unpack: [P, C] -> NCHW --------------------------
__global__ void unpack_kernel(const float* __restrict__ src, float* __restrict__ dst)
{
    __shared__ float s[32][33];
    int hw0 = blockIdx.x * 32;
    int c0  = blockIdx.y * 32;
    int b   = blockIdx.z;
    int tx = threadIdx.x, ty = threadIdx.y;
#pragma unroll
    for (int i = 0; i < 4; i++)
        s[ty + 8*i][tx] = src[(size_t)(b*HW_ + hw0 + ty + 8*i)*CDIM + c0 + tx];
    __syncthreads();
#pragma unroll
    for (int i = 0; i < 4; i++)
        dst[(size_t)(b*CDIM + c0 + ty + 8*i)*HW_ + hw0 + tx] = s[tx][ty + 8*i];
}

// ------------------------- tf32 tensor-core GEMM ---------------------------
// C[M,N] = epilogue( A[M,K] @ W[N,K]^T + bias )
// Block tile 128x128, K-tile 32, 8 warps (2 M x 4 N), warp tile 64x32.
// mma.sync.aligned.m16n8k8.row.col.f32.tf32.tf32.f32, cp.async double buffer.
#define GP 36                    // smem row pitch (floats) — conflict-free
#define SSTAGE (256*GP)          // floats per stage (A 128 rows + B 128 rows)

__device__ __forceinline__ uint32_t f2tf(float x) {
    uint32_t r;
    asm("cvt.rna.tf32.f32 %0, %1;" : "=r"(r) : "f"(x));
    return r;
}

__device__ __forceinline__ void mma_tf32(float c[4], uint32_t a0, uint32_t a1,
                                         uint32_t a2, uint32_t a3,
                                         uint32_t b0, uint32_t b1)
{
    asm volatile(
        "mma.sync.aligned.m16n8k8.row.col.f32.tf32.tf32.f32 "
        "{%0,%1,%2,%3}, {%4,%5,%6,%7}, {%8,%9}, {%0,%1,%2,%3};\n"
        : "+f"(c[0]), "+f"(c[1]), "+f"(c[2]), "+f"(c[3])
        : "r"(a0), "r"(a1), "r"(a2), "r"(a3), "r"(b0), "r"(b1));
}

__device__ __forceinline__ void cp16(uint32_t dst_smem, const float* src) {
    asm volatile("cp.async.cg.shared.global [%0], [%1], 16;\n"
                 :: "r"(dst_smem), "l"(src));
}

__global__ __launch_bounds__(256)
void gemm_mma(const float* __restrict__ A, const float* __restrict__ Wm,
              const float* __restrict__ bias, const float* __restrict__ res,
              float* __restrict__ C, int M, int N, int K, float alpha, int gelu)
{
    extern __shared__ float smem[];
    const uint32_t smem_base = (uint32_t)__cvta_generic_to_shared(smem);

    int bx = blockIdx.x, by = blockIdx.y;
    int tid  = threadIdx.x;
    int warp = tid >> 5, lane = tid & 31;
    int wm = warp >> 2;            // 0..1  (M)
    int wn = warp & 3;             // 0..3  (N)
    int g  = lane >> 2, c = lane & 3;

    const float* Ab = A  + (size_t)by * 128 * K;
    const float* Wb = Wm + (size_t)bx * 128 * K;

    float acc[4][4][4];
#pragma unroll
    for (int i = 0; i < 4; i++)
#pragma unroll
        for (int j = 0; j < 4; j++)
#pragma unroll
            for (int r = 0; r < 4; r++) acc[i][j][r] = 0.f;

    const int nk = K >> 5;         // K / 32

    // global->smem loader: 4 chunks of 16B per thread per (A|B) tile
    // chunk id = tid + t*256 ; row = chunk>>3 ; kc = (chunk&7)*4
    auto issue = [&](int kt, int buf) {
        int k0 = kt << 5;
        uint32_t sa = smem_base + (uint32_t)(buf * SSTAGE) * 4u;
        uint32_t sb = sa + 128u * GP * 4u;
#pragma unroll
        for (int t = 0; t < 4; t++) {
            int chunk = tid + t * 256;
            int row = chunk >> 3;
            int kc  = (chunk & 7) << 2;
            cp16(sa + (uint32_t)(row * GP + kc) * 4u, Ab + (size_t)row * K + k0 + kc);
            cp16(sb + (uint32_t)(row * GP + kc) * 4u, Wb + (size_t)row * K + k0 + kc);
        }
        asm volatile("cp.async.commit_group;\n");
    };

    issue(0, 0);

    for (int kt = 0; kt < nk; kt++) {
        asm volatile("cp.async.wait_group 0;\n");
        __syncthreads();
        if (kt + 1 < nk) issue(kt + 1, (kt + 1) & 1);

        const float* As = smem + (kt & 1) * SSTAGE;
        const float* Bs = As + 128 * GP;
        int mrow = wm * 64;
        int ncol = wn * 32;

#pragma unroll
        for (int ks = 0; ks < 4; ks++) {
            int k0 = ks << 3;
            uint32_t af[4][4];
#pragma unroll
            for (int mt = 0; mt < 4; mt++) {
                int r0 = mrow + mt * 16 + g;
                af[mt][0] = f2tf(As[r0 * GP + k0 + c]);
                af[mt][1] = f2tf(As[(r0 + 8) * GP + k0 + c]);
                af[mt][2] = f2tf(As[r0 * GP + k0 + c + 4]);
                af[mt][3] = f2tf(As[(r0 + 8) * GP + k0 + c + 4]);
            }
            uint32_t bf[4][2];
#pragma unroll
            for (int nt = 0; nt < 4; nt++) {
                int n0 = ncol + nt * 8 + g;
                bf[nt][0] = f2tf(Bs[n0 * GP + k0 + c]);
                bf[nt][1] = f2tf(Bs[n0 * GP + k0 + c + 4]);
            }
#pragma unroll
            for (int mt = 0; mt < 4; mt++)
#pragma unroll
                for (int nt = 0; nt < 4; nt++)
                    mma_tf32(acc[mt][nt], af[mt][0], af[mt][1], af[mt][2], af[mt][3],
                             bf[nt][0], bf[nt][1]);
        }
        __syncthreads();
    }

    // epilogue
#pragma unroll
    for (int mt = 0; mt < 4; mt++) {
#pragma unroll
        for (int nt = 0; nt < 4; nt++) {
            int row = by * 128 + wm * 64 + mt * 16 + g;
            int col = bx * 128 + wn * 32 + nt * 8 + 2 * c;
#pragma unroll
            for (int half = 0; half < 2; half++) {     // half=0 -> row, half=1 -> row+8
                int rr = row + half * 8;
                float v0 = (acc[mt][nt][half*2+0] + bias[col])     * alpha;
                float v1 = (acc[mt][nt][half*2+1] + bias[col + 1]) * alpha;
                if (gelu) {
                    v0 = 0.5f * v0 * (1.0f + erff(v0 * 0.70710678118654752f));
                    v1 = 0.5f * v1 * (1.0f + erff(v1 * 0.70710678118654752f));
                }
                if (res) {
                    v0 += res[(size_t)rr * N + col];
                    v1 += res[(size_t)rr * N + col + 1];
                }
                float2 o = {v0, v1};
                *(float2*)&C[(size_t)rr * N + col] = o;
            }
        }
    }
}

// ------------------------- LayerNorm + window partition --------------------
__global__ void ln_part_kernel(const float* __restrict__ x, const float* __restrict__ g,
                               const float* __restrict__ b, float* __restrict__ out,
                               int to_window)
{
    int warp = threadIdx.x >> 5, lane = threadIdx.x & 31;
    int p = blockIdx.x * 8 + warp;
    const float* row = x + (size_t)p * CDIM;
    float4 v0 = *(const float4*)(row + lane*4);
    float4 v1 = *(const float4*)(row + 128 + lane*4);
    float s  = v0.x+v0.y+v0.z+v0.w + v1.x+v1.y+v1.z+v1.w;
    float sq = v0.x*v0.x+v0.y*v0.y+v0.z*v0.z+v0.w*v0.w
             + v1.x*v1.x+v1.y*v1.y+v1.z*v1.z+v1.w*v1.w;
#pragma unroll
    for (int o = 16; o; o >>= 1) {
        s  += __shfl_xor_sync(0xffffffffu, s,  o);
        sq += __shfl_xor_sync(0xffffffffu, sq, o);
    }
    float mean = s * (1.0f/CDIM);
    float var  = sq * (1.0f/CDIM) - mean*mean;
    float rstd = rsqrtf(var + 1e-5f);
    int r = to_window ? win_row(p) : p;
    float* orow = out + (size_t)r * CDIM;
    int c0 = lane*4;
    float4 o0, o1;
    o0.x = (v0.x-mean)*rstd*g[c0+0] + b[c0+0];
    o0.y = (v0.y-mean)*rstd*g[c0+1] + b[c0+1];
    o0.z = (v0.z-mean)*rstd*g[c0+2] + b[c0+2];
    o0.w = (v0.w-mean)*rstd*g[c0+3] + b[c0+3];
    o1.x = (v1.x-mean)*rstd*g[c0+128+0] + b[c0+128+0];
    o1.y = (v1.y-mean)*rstd*g[c0+128+1] + b[c0+128+1];
    o1.z = (v1.z-mean)*rstd*g[c0+128+2] + b[c0+128+2];
    o1.w = (v1.w-mean)*rstd*g[c0+128+3] + b[c0+128+3];
    *(float4*)(orow + c0)       = o0;
    *(float4*)(orow + 128 + c0) = o1;
}

// ------------------------- residual + LN2 (window-reverse) -----------------
__global__ void res_ln2_kernel(const float* __restrict__ proj, const float* __restrict__ sc,
                               const float* __restrict__ g, const float* __restrict__ b,
                               float* __restrict__ zt, float* __restrict__ ln2)
{
    int warp = threadIdx.x >> 5, lane = threadIdx.x & 31;
    int p = blockIdx.x * 8 + warp;
    int r = win_row(p);
    const float* prow = proj + (size_t)r * CDIM;
    const float* srow = sc   + (size_t)p * CDIM;
    int c0 = lane*4;
    float4 a0 = *(const float4*)(prow + c0);
    float4 a1 = *(const float4*)(prow + 128 + c0);
    float4 s0 = *(const float4*)(srow + c0);
    float4 s1 = *(const float4*)(srow + 128 + c0);
    float4 v0 = {a0.x+s0.x, a0.y+s0.y, a0.z+s0.z, a0.w+s0.w};
    float4 v1 = {a1.x+s1.x, a1.y+s1.y, a1.z+s1.z, a1.w+s1.w};
    *(float4*)(zt + (size_t)p*CDIM + c0)       = v0;
    *(float4*)(zt + (size_t)p*CDIM + 128 + c0) = v1;
    float s  = v0.x+v0.y+v0.z+v0.w + v1.x+v1.y+v1.z+v1.w;
    float sq = v0.x*v0.x+v0.y*v0.y+v0.z*v0.z+v0.w*v0.w
             + v1.x*v1.x+v1.y*v1.y+v1.z*v1.z+v1.w*v1.w;
#pragma unroll
    for (int o = 16; o; o >>= 1) {
        s  += __shfl_xor_sync(0xffffffffu, s,  o);
        sq += __shfl_xor_sync(0xffffffffu, sq, o);
    }
    float mean = s * (1.0f/CDIM);
    float var  = sq * (1.0f/CDIM) - mean*mean;
    float rstd = rsqrtf(var + 1e-5f);
    float* orow = ln2 + (size_t)p * CDIM;
    float4 o0, o1;
    o0.x=(v0.x-mean)*rstd*g[c0+0]+b[c0+0];  o0.y=(v0.y-mean)*rstd*g[c0+1]+b[c0+1];
    o0.z=(v0.z-mean)*rstd*g[c0+2]+b[c0+2];  o0.w=(v0.w-mean)*rstd*g[c0+3]+b[c0+3];
    o1.x=(v1.x-mean)*rstd*g[c0+128+0]+b[c0+128+0];  o1.y=(v1.y-mean)*rstd*g[c0+128+1]+b[c0+128+1];
    o1.z=(v1.z-mean)*rstd*g[c0+128+2]+b[c0+128+2];  o1.w=(v1.w-mean)*rstd*g[c0+128+3]+b[c0+128+3];
    *(float4*)(orow + c0)       = o0;
    *(float4*)(orow + 128 + c0) = o1;
}

// ------------------------- windowed attention ------------------------------
__global__ __launch_bounds__(128)
void attn_kernel(const float* __restrict__ q, const float* __restrict__ k,
                 const float* __restrict__ v, const float* __restrict__ rpb,
                 float* __restrict__ out)
{
    __shared__ float qs[64][33];
    __shared__ float ks[64][33];
    __shared__ float vs[64][33];
    __shared__ float S [64][65];
    int win = blockIdx.x, h = blockIdx.y;
    int tid = threadIdx.x;
    size_t base = ((size_t)win * 64) * CDIM + h * HD;

    for (int idx = tid; idx < 64*HD; idx += 128) {
        int n = idx >> 5, d = idx & 31;
        qs[n][d] = q[base + (size_t)n*CDIM + d];
        ks[n][d] = k[base + (size_t)n*CDIM + d];
        vs[n][d] = v[base + (size_t)n*CDIM + d];
    }
    __syncthreads();

    for (int idx = tid; idx < 64*64; idx += 128) {
        int n = idx >> 6, m = idx & 63;
        float s = 0.f;
#pragma unroll
        for (int d = 0; d < HD; d++) s = fmaf(qs[n][d], ks[m][d], s);
        int di = (n >> 3) - (m >> 3) + 7;
        int dj = (n & 7)  - (m & 7)  + 7;
        s += rpb[(di*15 + dj)*NHEAD + h];
        S[n][m] = s;
    }
    __syncthreads();

    if (tid < 64) {
        int n = tid;
        float mx = -1e30f;
#pragma unroll
        for (int m = 0; m < 64; m++) mx = fmaxf(mx, S[n][m]);
        float sum = 0.f;
#pragma unroll
        for (int m = 0; m < 64; m++) { float e = expf(S[n][m] - mx); S[n][m] = e; sum += e; }
        float inv = 1.0f / sum;
#pragma unroll
        for (int m = 0; m < 64; m++) S[n][m] *= inv;
    }
    __syncthreads();

    for (int idx = tid; idx < 64*HD; idx += 128) {
        int n = idx >> 5, d = idx & 31;
        float o = 0.f;
#pragma unroll
        for (int m = 0; m < 64; m++) o = fmaf(S[n][m], vs[m][d], o);
        out[base + (size_t)n*CDIM + d] = o;
    }
}

// ---------------------------------------------------------------------------
extern "C" void kernel_launch(void* const* d_in, const int* in_sizes, int n_in,
                              void* d_out, int out_size)
{
    const float* LH      = (const float*)d_in[0];
    const float* HL      = (const float*)d_in[1];
    const float* HH      = (const float*)d_in[2];
    const float* Spat    = (const float*)d_in[3];
    const float* w_hllh  = (const float*)d_in[4];
    const float* b_hllh  = (const float*)d_in[5];
    const float* w_hh    = (const float*)d_in[6];
    const float* b_hh    = (const float*)d_in[7];
    const float* w_spat  = (const float*)d_in[8];
    const float* b_spat  = (const float*)d_in[9];
    const float* ln1x_g  = (const float*)d_in[10];
    const float* ln1x_b  = (const float*)d_in[11];
    const float* ln1y_g  = (const float*)d_in[12];
    const float* ln1y_b  = (const float*)d_in[13];
    const float* qkv_w   = (const float*)d_in[14];
    const float* qkv_b   = (const float*)d_in[15];
    const float* qkv2_w  = (const float*)d_in[16];
    const float* qkv2_b  = (const float*)d_in[17];
    const float* qkv3_w  = (const float*)d_in[18];
    const float* qkv3_b  = (const float*)d_in[19];
    const float* proj_w  = (const float*)d_in[20];
    const float* proj_b  = (const float*)d_in[21];
    const float* rpb     = (const float*)d_in[22];
    const float* ln2_g   = (const float*)d_in[23];
    const float* ln2_b   = (const float*)d_in[24];
    const float* fc1_w   = (const float*)d_in[25];
    const float* fc1_b   = (const float*)d_in[26];
    const float* fc2_w   = (const float*)d_in[27];
    const float* fc2_b   = (const float*)d_in[28];
    float* out = (float*)d_out;

    float *inx, *iny, *inz, *x, *y, *xn, *yn, *shrt, *q, *k, *v, *ao, *po, *zt, *ln2, *hbuf, *zt2;
    cudaGetSymbolAddress((void**)&inx,  g_inx);
    cudaGetSymbolAddress((void**)&iny,  g_iny);
    cudaGetSymbolAddress((void**)&inz,  g_inz);
    cudaGetSymbolAddress((void**)&x,    g_x);
    cudaGetSymbolAddress((void**)&y,    g_y);
    cudaGetSymbolAddress((void**)&xn,   g_xn);
    cudaGetSymbolAddress((void**)&yn,   g_yn);
    cudaGetSymbolAddress((void**)&shrt, g_short);
    cudaGetSymbolAddress((void**)&q,    g_q);
    cudaGetSymbolAddress((void**)&k,    g_k);
    cudaGetSymbolAddress((void**)&v,    g_v);
    cudaGetSymbolAddress((void**)&ao,   g_ao);
    cudaGetSymbolAddress((void**)&po,   g_po);
    cudaGetSymbolAddress((void**)&zt,   g_zt);
    cudaGetSymbolAddress((void**)&ln2,  g_ln2);
    cudaGetSymbolAddress((void**)&hbuf, g_h);
    cudaGetSymbolAddress((void**)&zt2,  g_zt2);

    static int smem_set = 0;
    const int GEMM_SMEM = 2 * SSTAGE * 4;     // 73728 bytes
    if (!smem_set) {
        cudaFuncSetAttribute(gemm_mma, cudaFuncAttributeMaxDynamicSharedMemorySize, GEMM_SMEM);
        smem_set = 1;
    }

    dim3 tb(32, 8);
    const int M = P_TOT;
    const float qscale = 0.17677669529663688f;   // 32^-0.5

    // pack NCHW -> row-major
    pack_kernel<<<dim3(HW_/32, 2, B_), tb>>>(LH,   inx, 64, 128, 0);
    pack_kernel<<<dim3(HW_/32, 2, B_), tb>>>(HL,   inx, 64, 128, 64);
    pack_kernel<<<dim3(HW_/32, 2, B_), tb>>>(HH,   inz, 64, 64, 0);
    pack_kernel<<<dim3(HW_/32, 2, B_), tb>>>(Spat, iny, 64, 64, 0);

    // 1x1 convs
    gemm_mma<<<dim3(2, M/128), 256, GEMM_SMEM>>>(inx, w_hllh, b_hllh, nullptr, x,    M, 256, 128, 1.f, 0);
    gemm_mma<<<dim3(2, M/128), 256, GEMM_SMEM>>>(inz, w_hh,   b_hh,   nullptr, shrt, M, 256, 64,  1.f, 0);
    gemm_mma<<<dim3(2, M/128), 256, GEMM_SMEM>>>(iny, w_spat, b_spat, nullptr, y,    M, 256, 64,  1.f, 0);

    // LN + window partition
    ln_part_kernel<<<M/8, 256>>>(x, ln1x_g, ln1x_b, xn, 1);
    ln_part_kernel<<<M/8, 256>>>(y, ln1y_g, ln1y_b, yn, 1);

    // q/k/v projections (q scaled by hd^-0.5)
    gemm_mma<<<dim3(2, M/128), 256, GEMM_SMEM>>>(xn, qkv_w,  qkv_b,  nullptr, q, M, 256, 256, qscale, 0);
    gemm_mma<<<dim3(2, M/128), 256, GEMM_SMEM>>>(yn, qkv2_w, qkv2_b, nullptr, k, M, 256, 256, 1.f, 0);
    gemm_mma<<<dim3(2, M/128), 256, GEMM_SMEM>>>(yn, qkv3_w, qkv3_b, nullptr, v, M, 256, 256, 1.f, 0);

    // windowed attention
    attn_kernel<<<dim3(2048, NHEAD), 128>>>(q, k, v, rpb, ao);

    // output projection
    gemm_mma<<<dim3(2, M/128), 256, GEMM_SMEM>>>(ao, proj_w, proj_b, nullptr, po, M, 256, 256, 1.f, 0);

    // window reverse + residual + LN2
    res_ln2_kernel<<<M/8, 256>>>(po, shrt, ln2_g, ln2_b, zt, ln2);

    // MLP
    gemm_mma<<<dim3(8, M/128), 256, GEMM_SMEM>>>(ln2,  fc1_w, fc1_b, nullptr, hbuf, M, HID, 256, 1.f, 1);
    gemm_mma<<<dim3(2, M/128), 256, GEMM_SMEM>>>(hbuf, fc2_w, fc2_b, zt,      zt2,  M, 256, HID, 1.f, 0);

    // [P,C] -> NCHW
    unpack_kernel<<<dim3(HW_/32, 8, B_), tb>>>(zt2, out);
}

// round 3
// speedup vs baseline: 2.8890x; 1.2118x over previous
#include <cuda_runtime.h>
#include <cuda_bf16.h>
#include <math.h>
#include <stdint.h>

// ---------------------------------------------------------------------------
// WaveletSwinTransformerBlock — tf32 tensor-core GEMMs, cvt-free inner loop
// ---------------------------------------------------------------------------

#define B_     8
#define H_     128
#define W_     128
#define HW_    (H_*W_)           // 16384
#define P_TOT  (B_*HW_)          // 131072
#define CDIM   256
#define NHEAD  8
#define HD     32
#define HID    1024

// ------------------------- scratch buffers (static) ------------------------
__device__ float g_inx[(size_t)P_TOT*128];
__device__ float g_iny[(size_t)P_TOT*64];
__device__ float g_inz[(size_t)P_TOT*64];
__device__ float g_x    [(size_t)P_TOT*CDIM];
__device__ float g_y    [(size_t)P_TOT*CDIM];
__device__ float g_xn   [(size_t)P_TOT*CDIM];
__device__ float g_yn   [(size_t)P_TOT*CDIM];
__device__ float g_short[(size_t)P_TOT*CDIM];
__device__ float g_q    [(size_t)P_TOT*CDIM];
__device__ float g_k    [(size_t)P_TOT*CDIM];
__device__ float g_v    [(size_t)P_TOT*CDIM];
__device__ float g_ao   [(size_t)P_TOT*CDIM];
__device__ float g_po   [(size_t)P_TOT*CDIM];
__device__ float g_zt   [(size_t)P_TOT*CDIM];
__device__ float g_ln2  [(size_t)P_TOT*CDIM];
__device__ float g_h    [(size_t)P_TOT*HID];
__device__ float g_zt2  [(size_t)P_TOT*CDIM];

// tf32-rounded weights, concatenated
#define WO_HLLH 0
#define WO_HH   32768
#define WO_SPAT 49152
#define WO_QKV  65536
#define WO_QKV2 131072
#define WO_QKV3 196608
#define WO_PROJ 262144
#define WO_FC1  327680
#define WO_FC2  589824
#define W_TOT   851968
__device__ float g_w[W_TOT];

__device__ __forceinline__ float rtf(float x) {
    uint32_t r;
    asm("cvt.rna.tf32.f32 %0, %1;" : "=r"(r) : "f"(x));
    return __uint_as_float(r);
}

__device__ __forceinline__ int win_row(int p) {
    int b  = p >> 14;
    int hw = p & 16383;
    int h  = hw >> 7, w = hw & 127;
    int win = (b << 8) | ((h >> 3) << 4) | (w >> 3);
    int tok = ((h & 7) << 3) | (w & 7);
    return (win << 6) | tok;
}

// ------------------------- weight pre-rounding -----------------------------
__global__ void round_w_kernel(const float* w0, const float* w1, const float* w2,
                               const float* w3, const float* w4, const float* w5,
                               const float* w6, const float* w7, const float* w8,
                               float* dst)
{
    int i = blockIdx.x * 256 + threadIdx.x;
    if (i >= W_TOT) return;
    float v;
    if      (i < WO_HH)   v = w0[i - WO_HLLH];
    else if (i < WO_SPAT) v = w1[i - WO_HH];
    else if (i < WO_QKV)  v = w2[i - WO_SPAT];
    else if (i < WO_QKV2) v = w3[i - WO_QKV];
    else if (i < WO_QKV3) v = w4[i - WO_QKV2];
    else if (i < WO_PROJ) v = w5[i - WO_QKV3];
    else if (i < WO_FC1)  v = w6[i - WO_PROJ];
    else if (i < WO_FC2)  v = w7[i - WO_FC1];
    else                  v = w8[i - WO_FC2];
    dst[i] = rtf(v);
}

// ------------------------- pack: NCHW -> [P, Cin] (tf32-rounded) -----------
__global__ void pack_kernel(const float* __restrict__ src, float* __restrict__ dst,
                            int Cin, int rowStride, int colOff)
{
    __shared__ float s[32][33];
    int hw0 = blockIdx.x * 32;
    int c0  = blockIdx.y * 32;
    int b   = blockIdx.z;
    int tx = threadIdx.x, ty = threadIdx.y;
#pragma unroll
    for (int i = 0; i < 4; i++)
        s[ty + 8*i][tx] = src[((size_t)(b*Cin + c0 + ty + 8*i))*HW_ + hw0 + tx];
    __syncthreads();
#pragma unroll
    for (int i = 0; i < 4; i++)
        dst[(size_t)(b*HW_ + hw0 + ty + 8*i)*rowStride + colOff + c0 + tx] = rtf(s[tx][ty + 8*i]);
}

// ------------------------- unpack: [P, C] -> NCHW --------------------------
__global__ void unpack_kernel(const float* __restrict__ src, float* __restrict__ dst)
{
    __shared__ float s[32][33];
    int hw0 = blockIdx.x * 32;
    int c0  = blockIdx.y * 32;
    int b   = blockIdx.z;
    int tx = threadIdx.x, ty = threadIdx.y;
#pragma unroll
    for (int i = 0; i < 4; i++)
        s[ty + 8*i][tx] = src[(size_t)(b*HW_ + hw0 + ty + 8*i)*CDIM + c0 + tx];
    __syncthreads();
#pragma unroll
    for (int i = 0; i < 4; i++)
        dst[(size_t)(b*CDIM + c0 + ty + 8*i)*HW_ + hw0 + tx] = s[tx][ty + 8*i];
}

// ------------------------- tf32 tensor-core GEMM ---------------------------
// All operands must already be tf32-rounded fp32.
#define GP 36
#define SSTAGE (256*GP)

__device__ __forceinline__ void mma_tf32(float c[4], uint32_t a0, uint32_t a1,
                                         uint32_t a2, uint32_t a3,
                                         uint32_t b0, uint32_t b1)
{
    asm volatile(
        "mma.sync.aligned.m16n8k8.row.col.f32.tf32.tf32.f32 "
        "{%0,%1,%2,%3}, {%4,%5,%6,%7}, {%8,%9}, {%0,%1,%2,%3};\n"
        : "+f"(c[0]), "+f"(c[1]), "+f"(c[2]), "+f"(c[3])
        : "r"(a0), "r"(a1), "r"(a2), "r"(a3), "r"(b0), "r"(b1));
}

__device__ __forceinline__ void cp16(uint32_t dst_smem, const float* src) {
    asm volatile("cp.async.cg.shared.global [%0], [%1], 16;\n"
                 :: "r"(dst_smem), "l"(src));
}

__global__ __launch_bounds__(256, 2)
void gemm_mma(const float* __restrict__ A, const float* __restrict__ Wm,
              const float* __restrict__ bias, const float* __restrict__ res,
              float* __restrict__ C, int M, int N, int K, float alpha,
              int gelu, int round_out)
{
    extern __shared__ float smem[];
    const uint32_t smem_base = (uint32_t)__cvta_generic_to_shared(smem);

    int bx = blockIdx.x, by = blockIdx.y;
    int tid  = threadIdx.x;
    int warp = tid >> 5, lane = tid & 31;
    int wm = warp >> 2;
    int wn = warp & 3;
    int g  = lane >> 2, c = lane & 3;

    const float* Ab = A  + (size_t)by * 128 * K;
    const float* Wb = Wm + (size_t)bx * 128 * K;

    float acc[4][4][4];
#pragma unroll
    for (int i = 0; i < 4; i++)
#pragma unroll
        for (int j = 0; j < 4; j++)
#pragma unroll
            for (int r = 0; r < 4; r++) acc[i][j][r] = 0.f;

    const int nk = K >> 5;

    auto issue = [&](int kt, int buf) {
        int k0 = kt << 5;
        uint32_t sa = smem_base + (uint32_t)(buf * SSTAGE) * 4u;
        uint32_t sb = sa + 128u * GP * 4u;
#pragma unroll
        for (int t = 0; t < 4; t++) {
            int chunk = tid + t * 256;
            int row = chunk >> 3;
            int kc  = (chunk & 7) << 2;
            cp16(sa + (uint32_t)(row * GP + kc) * 4u, Ab + (size_t)row * K + k0 + kc);
            cp16(sb + (uint32_t)(row * GP + kc) * 4u, Wb + (size_t)row * K + k0 + kc);
        }
        asm volatile("cp.async.commit_group;\n");
    };

    issue(0, 0);

    for (int kt = 0; kt < nk; kt++) {
        asm volatile("cp.async.wait_group 0;\n");
        __syncthreads();
        if (kt + 1 < nk) issue(kt + 1, (kt + 1) & 1);

        const float* As = smem + (kt & 1) * SSTAGE;
        const float* Bs = As + 128 * GP;
        int mrow = wm * 64;
        int ncol = wn * 32;

#pragma unroll
        for (int ks = 0; ks < 4; ks++) {
            int k0 = ks << 3;
            uint32_t af[4][4];
#pragma unroll
            for (int mt = 0; mt < 4; mt++) {
                int r0 = mrow + mt * 16 + g;
                af[mt][0] = __float_as_uint(As[r0 * GP + k0 + c]);
                af[mt][1] = __float_as_uint(As[(r0 + 8) * GP + k0 + c]);
                af[mt][2] = __float_as_uint(As[r0 * GP + k0 + c + 4]);
                af[mt][3] = __float_as_uint(As[(r0 + 8) * GP + k0 + c + 4]);
            }
            uint32_t bf[4][2];
#pragma unroll
            for (int nt = 0; nt < 4; nt++) {
                int n0 = ncol + nt * 8 + g;
                bf[nt][0] = __float_as_uint(Bs[n0 * GP + k0 + c]);
                bf[nt][1] = __float_as_uint(Bs[n0 * GP + k0 + c + 4]);
            }
#pragma unroll
            for (int mt = 0; mt < 4; mt++)
#pragma unroll
                for (int nt = 0; nt < 4; nt++)
                    mma_tf32(acc[mt][nt], af[mt][0], af[mt][1], af[mt][2], af[mt][3],
                             bf[nt][0], bf[nt][1]);
        }
        __syncthreads();
    }

    // epilogue
#pragma unroll
    for (int mt = 0; mt < 4; mt++) {
#pragma unroll
        for (int nt = 0; nt < 4; nt++) {
            int row = by * 128 + wm * 64 + mt * 16 + g;
            int col = bx * 128 + wn * 32 + nt * 8 + 2 * c;
#pragma unroll
            for (int half = 0; half < 2; half++) {
                int rr = row + half * 8;
                float v0 = (acc[mt][nt][half*2+0] + bias[col])     * alpha;
                float v1 = (acc[mt][nt][half*2+1] + bias[col + 1]) * alpha;
                if (gelu) {
                    v0 = 0.5f * v0 * (1.0f + erff(v0 * 0.70710678118654752f));
                    v1 = 0.5f * v1 * (1.0f + erff(v1 * 0.70710678118654752f));
                }
                if (res) {
                    v0 += res[(size_t)rr * N + col];
                    v1 += res[(size_t)rr * N + col + 1];
                }
                if (round_out) { v0 = rtf(v0); v1 = rtf(v1); }
                float2 o = {v0, v1};
                *(float2*)&C[(size_t)rr * N + col] = o;
            }
        }
    }
}

// ------------------------- LayerNorm + window partition (rounds out) -------
__global__ void ln_part_kernel(const float* __restrict__ x, const float* __restrict__ g,
                               const float* __restrict__ b, float* __restrict__ out,
                               int to_window)
{
    int warp = threadIdx.x >> 5, lane = threadIdx.x & 31;
    int p = blockIdx.x * 8 + warp;
    const float* row = x + (size_t)p * CDIM;
    float4 v0 = *(const float4*)(row + lane*4);
    float4 v1 = *(const float4*)(row + 128 + lane*4);
    float s  = v0.x+v0.y+v0.z+v0.w + v1.x+v1.y+v1.z+v1.w;
    float sq = v0.x*v0.x+v0.y*v0.y+v0.z*v0.z+v0.w*v0.w
             + v1.x*v1.x+v1.y*v1.y+v1.z*v1.z+v1.w*v1.w;
#pragma unroll
    for (int o = 16; o; o >>= 1) {
        s  += __shfl_xor_sync(0xffffffffu, s,  o);
        sq += __shfl_xor_sync(0xffffffffu, sq, o);
    }
    float mean = s * (1.0f/CDIM);
    float var  = sq * (1.0f/CDIM) - mean*mean;
    float rstd = rsqrtf(var + 1e-5f);
    int r = to_window ? win_row(p) : p;
    float* orow = out + (size_t)r * CDIM;
    int c0 = lane*4;
    float4 o0, o1;
    o0.x = rtf((v0.x-mean)*rstd*g[c0+0] + b[c0+0]);
    o0.y = rtf((v0.y-mean)*rstd*g[c0+1] + b[c0+1]);
    o0.z = rtf((v0.z-mean)*rstd*g[c0+2] + b[c0+2]);
    o0.w = rtf((v0.w-mean)*rstd*g[c0+3] + b[c0+3]);
    o1.x = rtf((v1.x-mean)*rstd*g[c0+128+0] + b[c0+128+0]);
    o1.y = rtf((v1.y-mean)*rstd*g[c0+128+1] + b[c0+128+1]);
    o1.z = rtf((v1.z-mean)*rstd*g[c0+128+2] + b[c0+128+2]);
    o1.w = rtf((v1.w-mean)*rstd*g[c0+128+3] + b[c0+128+3]);
    *(float4*)(orow + c0)       = o0;
    *(float4*)(orow + 128 + c0) = o1;
}

// ------------------------- residual + LN2 (window-reverse) -----------------
__global__ void res_ln2_kernel(const float* __restrict__ proj, const float* __restrict__ sc,
                               const float* __restrict__ g, const float* __restrict__ b,
                               float* __restrict__ zt, float* __restrict__ ln2)
{
    int warp = threadIdx.x >> 5, lane = threadIdx.x & 31;
    int p = blockIdx.x * 8 + warp;
    int r = win_row(p);
    const float* prow = proj + (size_t)r * CDIM;
    const float* srow = sc   + (size_t)p * CDIM;
    int c0 = lane*4;
    float4 a0 = *(const float4*)(prow + c0);
    float4 a1 = *(const float4*)(prow + 128 + c0);
    float4 s0 = *(const float4*)(srow + c0);
    float4 s1 = *(const float4*)(srow + 128 + c0);
    float4 v0 = {a0.x+s0.x, a0.y+s0.y, a0.z+s0.z, a0.w+s0.w};
    float4 v1 = {a1.x+s1.x, a1.y+s1.y, a1.z+s1.z, a1.w+s1.w};
    *(float4*)(zt + (size_t)p*CDIM + c0)       = v0;
    *(float4*)(zt + (size_t)p*CDIM + 128 + c0) = v1;
    float s  = v0.x+v0.y+v0.z+v0.w + v1.x+v1.y+v1.z+v1.w;
    float sq = v0.x*v0.x+v0.y*v0.y+v0.z*v0.z+v0.w*v0.w
             + v1.x*v1.x+v1.y*v1.y+v1.z*v1.z+v1.w*v1.w;
#pragma unroll
    for (int o = 16; o; o >>= 1) {
        s  += __shfl_xor_sync(0xffffffffu, s,  o);
        sq += __shfl_xor_sync(0xffffffffu, sq, o);
    }
    float mean = s * (1.0f/CDIM);
    float var  = sq * (1.0f/CDIM) - mean*mean;
    float rstd = rsqrtf(var + 1e-5f);
    float* orow = ln2 + (size_t)p * CDIM;
    float4 o0, o1;
    o0.x=rtf((v0.x-mean)*rstd*g[c0+0]+b[c0+0]);  o0.y=rtf((v0.y-mean)*rstd*g[c0+1]+b[c0+1]);
    o0.z=rtf((v0.z-mean)*rstd*g[c0+2]+b[c0+2]);  o0.w=rtf((v0.w-mean)*rstd*g[c0+3]+b[c0+3]);
    o1.x=rtf((v1.x-mean)*rstd*g[c0+128+0]+b[c0+128+0]);  o1.y=rtf((v1.y-mean)*rstd*g[c0+128+1]+b[c0+128+1]);
    o1.z=rtf((v1.z-mean)*rstd*g[c0+128+2]+b[c0+128+2]);  o1.w=rtf((v1.w-mean)*rstd*g[c0+128+3]+b[c0+128+3]);
    *(float4*)(orow + c0)       = o0;
    *(float4*)(orow + 128 + c0) = o1;
}

// ------------------------- windowed attention (rounds out) -----------------
__global__ __launch_bounds__(128)
void attn_kernel(const float* __restrict__ q, const float* __restrict__ k,
                 const float* __restrict__ v, const float* __restrict__ rpb,
                 float* __restrict__ out)
{
    __shared__ float qs[64][33];
    __shared__ float ks[64][33];
    __shared__ float vs[64][33];
    __shared__ float S [64][65];
    int win = blockIdx.x, h = blockIdx.y;
    int tid = threadIdx.x;
    size_t base = ((size_t)win * 64) * CDIM + h * HD;

    for (int idx = tid; idx < 64*HD; idx += 128) {
        int n = idx >> 5, d = idx & 31;
        qs[n][d] = q[base + (size_t)n*CDIM + d];
        ks[n][d] = k[base + (size_t)n*CDIM + d];
        vs[n][d] = v[base + (size_t)n*CDIM + d];
    }
    __syncthreads();

    for (int idx = tid; idx < 64*64; idx += 128) {
        int n = idx >> 6, m = idx & 63;
        float s = 0.f;
#pragma unroll
        for (int d = 0; d < HD; d++) s = fmaf(qs[n][d], ks[m][d], s);
        int di = (n >> 3) - (m >> 3) + 7;
        int dj = (n & 7)  - (m & 7)  + 7;
        s += rpb[(di*15 + dj)*NHEAD + h];
        S[n][m] = s;
    }
    __syncthreads();

    if (tid < 64) {
        int n = tid;
        float mx = -1e30f;
#pragma unroll
        for (int m = 0; m < 64; m++) mx = fmaxf(mx, S[n][m]);
        float sum = 0.f;
#pragma unroll
        for (int m = 0; m < 64; m++) { float e = expf(S[n][m] - mx); S[n][m] = e; sum += e; }
        float inv = 1.0f / sum;
#pragma unroll
        for (int m = 0; m < 64; m++) S[n][m] *= inv;
    }
    __syncthreads();

    for (int idx = tid; idx < 64*HD; idx += 128) {
        int n = idx >> 5, d = idx & 31;
        float o = 0.f;
#pragma unroll
        for (int m = 0; m < 64; m++) o = fmaf(S[n][m], vs[m][d], o);
        out[base + (size_t)n*CDIM + d] = rtf(o);
    }
}

// ---------------------------------------------------------------------------
extern "C" void kernel_launch(void* const* d_in, const int* in_sizes, int n_in,
                              void* d_out, int out_size)
{
    const float* LH      = (const float*)d_in[0];
    const float* HL      = (const float*)d_in[1];
    const float* HH      = (const float*)d_in[2];
    const float* Spat    = (const float*)d_in[3];
    const float* w_hllh  = (const float*)d_in[4];
    const float* b_hllh  = (const float*)d_in[5];
    const float* w_hh    = (const float*)d_in[6];
    const float* b_hh    = (const float*)d_in[7];
    const float* w_spat  = (const float*)d_in[8];
    const float* b_spat  = (const float*)d_in[9];
    const float* ln1x_g  = (const float*)d_in[10];
    const float* ln1x_b  = (const float*)d_in[11];
    const float* ln1y_g  = (const float*)d_in[12];
    const float* ln1y_b  = (const float*)d_in[13];
    const float* qkv_w   = (const float*)d_in[14];
    const float* qkv_b   = (const float*)d_in[15];
    const float* qkv2_w  = (const float*)d_in[16];
    const float* qkv2_b  = (const float*)d_in[17];
    const float* qkv3_w  = (const float*)d_in[18];
    const float* qkv3_b  = (const float*)d_in[19];
    const float* proj_w  = (const float*)d_in[20];
    const float* proj_b  = (const float*)d_in[21];
    const float* rpb     = (const float*)d_in[22];
    const float* ln2_g   = (const float*)d_in[23];
    const float* ln2_b   = (const float*)d_in[24];
    const float* fc1_w   = (const float*)d_in[25];
    const float* fc1_b   = (const float*)d_in[26];
    const float* fc2_w   = (const float*)d_in[27];
    const float* fc2_b   = (const float*)d_in[28];
    float* out = (float*)d_out;

    float *inx, *iny, *inz, *x, *y, *xn, *yn, *shrt, *q, *k, *v, *ao, *po, *zt, *ln2, *hbuf, *zt2, *wbuf;
    cudaGetSymbolAddress((void**)&inx,  g_inx);
    cudaGetSymbolAddress((void**)&iny,  g_iny);
    cudaGetSymbolAddress((void**)&inz,  g_inz);
    cudaGetSymbolAddress((void**)&x,    g_x);
    cudaGetSymbolAddress((void**)&y,    g_y);
    cudaGetSymbolAddress((void**)&xn,   g_xn);
    cudaGetSymbolAddress((void**)&yn,   g_yn);
    cudaGetSymbolAddress((void**)&shrt, g_short);
    cudaGetSymbolAddress((void**)&q,    g_q);
    cudaGetSymbolAddress((void**)&k,    g_k);
    cudaGetSymbolAddress((void**)&v,    g_v);
    cudaGetSymbolAddress((void**)&ao,   g_ao);
    cudaGetSymbolAddress((void**)&po,   g_po);
    cudaGetSymbolAddress((void**)&zt,   g_zt);
    cudaGetSymbolAddress((void**)&ln2,  g_ln2);
    cudaGetSymbolAddress((void**)&hbuf, g_h);
    cudaGetSymbolAddress((void**)&zt2,  g_zt2);
    cudaGetSymbolAddress((void**)&wbuf, g_w);

    static int smem_set = 0;
    const int GEMM_SMEM = 2 * SSTAGE * 4;
    if (!smem_set) {
        cudaFuncSetAttribute(gemm_mma, cudaFuncAttributeMaxDynamicSharedMemorySize, GEMM_SMEM);
        smem_set = 1;
    }

    dim3 tb(32, 8);
    const int M = P_TOT;
    const float qscale = 0.17677669529663688f;

    // round weights to tf32
    round_w_kernel<<<(W_TOT + 255)/256, 256>>>(w_hllh, w_hh, w_spat, qkv_w, qkv2_w,
                                               qkv3_w, proj_w, fc1_w, fc2_w, wbuf);

    // pack NCHW -> row-major (tf32-rounded)
    pack_kernel<<<dim3(HW_/32, 2, B_), tb>>>(LH,   inx, 64, 128, 0);
    pack_kernel<<<dim3(HW_/32, 2, B_), tb>>>(HL,   inx, 64, 128, 64);
    pack_kernel<<<dim3(HW_/32, 2, B_), tb>>>(HH,   inz, 64, 64, 0);
    pack_kernel<<<dim3(HW_/32, 2, B_), tb>>>(Spat, iny, 64, 64, 0);

    // 1x1 convs
    gemm_mma<<<dim3(2, M/128), 256, GEMM_SMEM>>>(inx, wbuf+WO_HLLH, b_hllh, nullptr, x,    M, 256, 128, 1.f, 0, 0);
    gemm_mma<<<dim3(2, M/128), 256, GEMM_SMEM>>>(inz, wbuf+WO_HH,   b_hh,   nullptr, shrt, M, 256, 64,  1.f, 0, 0);
    gemm_mma<<<dim3(2, M/128), 256, GEMM_SMEM>>>(iny, wbuf+WO_SPAT, b_spat, nullptr, y,    M, 256, 64,  1.f, 0, 0);

    // LN + window partition (tf32-rounded out)
    ln_part_kernel<<<M/8, 256>>>(x, ln1x_g, ln1x_b, xn, 1);
    ln_part_kernel<<<M/8, 256>>>(y, ln1y_g, ln1y_b, yn, 1);

    // q/k/v projections
    gemm_mma<<<dim3(2, M/128), 256, GEMM_SMEM>>>(xn, wbuf+WO_QKV,  qkv_b,  nullptr, q, M, 256, 256, qscale, 0, 0);
    gemm_mma<<<dim3(2, M/128), 256, GEMM_SMEM>>>(yn, wbuf+WO_QKV2, qkv2_b, nullptr, k, M, 256, 256, 1.f, 0, 0);
    gemm_mma<<<dim3(2, M/128), 256, GEMM_SMEM>>>(yn, wbuf+WO_QKV3, qkv3_b, nullptr, v, M, 256, 256, 1.f, 0, 0);

    // windowed attention (tf32-rounded out)
    attn_kernel<<<dim3(2048, NHEAD), 128>>>(q, k, v, rpb, ao);

    // output projection
    gemm_mma<<<dim3(2, M/128), 256, GEMM_SMEM>>>(ao, wbuf+WO_PROJ, proj_b, nullptr, po, M, 256, 256, 1.f, 0, 0);

    // window reverse + residual + LN2 (ln2 tf32-rounded)
    res_ln2_kernel<<<M/8, 256>>>(po, shrt, ln2_g, ln2_b, zt, ln2);

    // MLP (fc1 output tf32-rounded)
    gemm_mma<<<dim3(8, M/128), 256, GEMM_SMEM>>>(ln2,  wbuf+WO_FC1, fc1_b, nullptr, hbuf, M, HID, 256, 1.f, 1, 1);
    gemm_mma<<<dim3(2, M/128), 256, GEMM_SMEM>>>(hbuf, wbuf+WO_FC2, fc2_b, zt,      zt2,  M, 256, HID, 1.f, 0, 0);

    // [P,C] -> NCHW
    unpack_kernel<<<dim3(HW_/32, 8, B_), tb>>>(zt2, out);
}

// round 5
// speedup vs baseline: 3.6603x; 1.2670x over previous
#include <cuda_runtime.h>
#include <cuda_fp16.h>
#include <math.h>
#include <stdint.h>

// ---------------------------------------------------------------------------
// WaveletSwinTransformerBlock — fp16 mma.sync (m16n8k16) GEMMs, fp32 accum
// ---------------------------------------------------------------------------

#define B_     8
#define H_     128
#define W_     128
#define HW_    (H_*W_)           // 16384
#define P_TOT  (B_*HW_)          // 131072
#define CDIM   256
#define NHEAD  8
#define HD     32
#define HID    1024

// ------------------------- scratch buffers (static) ------------------------
__device__ __half g_inx[(size_t)P_TOT*128];
__device__ __half g_iny[(size_t)P_TOT*64];
__device__ __half g_inz[(size_t)P_TOT*64];
__device__ float  g_x    [(size_t)P_TOT*CDIM];
__device__ float  g_y    [(size_t)P_TOT*CDIM];
__device__ __half g_xn   [(size_t)P_TOT*CDIM];
__device__ __half g_yn   [(size_t)P_TOT*CDIM];
__device__ float  g_short[(size_t)P_TOT*CDIM];
__device__ float  g_q    [(size_t)P_TOT*CDIM];
__device__ float  g_k    [(size_t)P_TOT*CDIM];
__device__ float  g_v    [(size_t)P_TOT*CDIM];
__device__ __half g_ao   [(size_t)P_TOT*CDIM];
__device__ float  g_po   [(size_t)P_TOT*CDIM];
__device__ float  g_zt   [(size_t)P_TOT*CDIM];
__device__ __half g_ln2  [(size_t)P_TOT*CDIM];
__device__ __half g_h    [(size_t)P_TOT*HID];
__device__ float  g_zt2  [(size_t)P_TOT*CDIM];

// fp16 weights, concatenated
#define WO_HLLH 0
#define WO_HH   32768
#define WO_SPAT 49152
#define WO_QKV  65536
#define WO_QKV2 131072
#define WO_QKV3 196608
#define WO_PROJ 262144
#define WO_FC1  327680
#define WO_FC2  589824
#define W_TOT   851968
__device__ __half g_w[W_TOT];

__device__ __forceinline__ int win_row(int p) {
    int b  = p >> 14;
    int hw = p & 16383;
    int h  = hw >> 7, w = hw & 127;
    int win = (b << 8) | ((h >> 3) << 4) | (w >> 3);
    int tok = ((h & 7) << 3) | (w & 7);
    return (win << 6) | tok;
}

// ------------------------- weight conversion -------------------------------
__global__ void conv_w_kernel(const float* w0, const float* w1, const float* w2,
                              const float* w3, const float* w4, const float* w5,
                              const float* w6, const float* w7, const float* w8,
                              __half* dst)
{
    int i = blockIdx.x * 256 + threadIdx.x;
    if (i >= W_TOT) return;
    float v;
    if      (i < WO_HH)   v = w0[i - WO_HLLH];
    else if (i < WO_SPAT) v = w1[i - WO_HH];
    else if (i < WO_QKV)  v = w2[i - WO_SPAT];
    else if (i < WO_QKV2) v = w3[i - WO_QKV];
    else if (i < WO_QKV3) v = w4[i - WO_QKV2];
    else if (i < WO_PROJ) v = w5[i - WO_QKV3];
    else if (i < WO_FC1)  v = w6[i - WO_PROJ];
    else if (i < WO_FC2)  v = w7[i - WO_FC1];
    else                  v = w8[i - WO_FC2];
    dst[i] = __float2half_rn(v);
}

// ------------------------- pack: NCHW -> [P, Cin] fp16 ---------------------
__global__ void pack_kernel(const float* __restrict__ src, __half* __restrict__ dst,
                            int Cin, int rowStride, int colOff)
{
    __shared__ float s[32][33];
    int hw0 = blockIdx.x * 32;
    int c0  = blockIdx.y * 32;
    int b   = blockIdx.z;
    int tx = threadIdx.x, ty = threadIdx.y;
#pragma unroll
    for (int i = 0; i < 4; i++)
        s[ty + 8*i][tx] = src[((size_t)(b*Cin + c0 + ty + 8*i))*HW_ + hw0 + tx];
    __syncthreads();
#pragma unroll
    for (int i = 0; i < 4; i++)
        dst[(size_t)(b*HW_ + hw0 + ty + 8*i)*rowStride + colOff + c0 + tx] =
            __float2half_rn(s[tx][ty + 8*i]);
}

// ------------------------- unpack: [P, C] -> NCHW --------------------------
__global__ void unpack_kernel(const float* __restrict__ src, float* __restrict__ dst)
{
    __shared__ float s[32][33];
    int hw0 = blockIdx.x * 32;
    int c0  = blockIdx.y * 32;
    int b   = blockIdx.z;
    int tx = threadIdx.x, ty = threadIdx.y;
#pragma unroll
    for (int i = 0; i < 4; i++)
        s[ty + 8*i][tx] = src[(size_t)(b*HW_ + hw0 + ty + 8*i)*CDIM + c0 + tx];
    __syncthreads();
#pragma unroll
    for (int i = 0; i < 4; i++)
        dst[(size_t)(b*CDIM + c0 + ty + 8*i)*HW_ + hw0 + tx] = s[tx][ty + 8*i];
}

// ------------------------- fp16 tensor-core GEMM ---------------------------
// C[M,N] = epilogue( A[M,K] @ W[N,K]^T + bias ), fp32 accumulate.
// Block 128x128, k-tile 32 halfs, 8 warps (2M x 4N), warp tile 64x32.
#define HP 40                        // smem pitch in halfs (20 words): conflict-free
#define HSTAGE (128*HP)              // halfs per matrix per stage
#define GSMEM  (2 * 2 * HSTAGE * 2)  // 2 stages * 2 matrices * bytes  = 40960

__device__ __forceinline__ void mma_f16(float c[4], uint32_t a0, uint32_t a1,
                                        uint32_t a2, uint32_t a3,
                                        uint32_t b0, uint32_t b1)
{
    asm volatile(
        "mma.sync.aligned.m16n8k16.row.col.f32.f16.f16.f32 "
        "{%0,%1,%2,%3}, {%4,%5,%6,%7}, {%8,%9}, {%0,%1,%2,%3};\n"
        : "+f"(c[0]), "+f"(c[1]), "+f"(c[2]), "+f"(c[3])
        : "r"(a0), "r"(a1), "r"(a2), "r"(a3), "r"(b0), "r"(b1));
}

__device__ __forceinline__ void cp16(uint32_t dst_smem, const __half* src) {
    asm volatile("cp.async.cg.shared.global [%0], [%1], 16;\n"
                 :: "r"(dst_smem), "l"(src));
}

__global__ __launch_bounds__(256, 2)
void gemm_h(const __half* __restrict__ A, const __half* __restrict__ Wm,
            const float* __restrict__ bias, const float* __restrict__ res,
            void* __restrict__ Cout, int M, int N, int K, float alpha,
            int gelu, int out_half)
{
    extern __shared__ __half smem[];
    const uint32_t smem_base = (uint32_t)__cvta_generic_to_shared(smem);

    int bx = blockIdx.x, by = blockIdx.y;
    int tid  = threadIdx.x;
    int warp = tid >> 5, lane = tid & 31;
    int wm = warp >> 2;
    int wn = warp & 3;
    int g  = lane >> 2, c = lane & 3;

    const __half* Ab = A  + (size_t)by * 128 * K;
    const __half* Wb = Wm + (size_t)bx * 128 * K;

    float acc[4][4][4];
#pragma unroll
    for (int i = 0; i < 4; i++)
#pragma unroll
        for (int j = 0; j < 4; j++)
#pragma unroll
            for (int r = 0; r < 4; r++) acc[i][j][r] = 0.f;

    const int nk = K >> 5;

    // loader: A tile 128x32 halfs = 512 x16B chunks; same for B
    auto issue = [&](int kt, int buf) {
        int k0 = kt << 5;
        uint32_t sa = smem_base + (uint32_t)(buf * 2 * HSTAGE) * 2u;
        uint32_t sb = sa + (uint32_t)HSTAGE * 2u;
#pragma unroll
        for (int i = 0; i < 2; i++) {
            int ch = tid + (i << 8);
            int row = ch >> 2;
            int c8  = (ch & 3) << 3;
            cp16(sa + (uint32_t)(row * HP + c8) * 2u, Ab + (size_t)row * K + k0 + c8);
            cp16(sb + (uint32_t)(row * HP + c8) * 2u, Wb + (size_t)row * K + k0 + c8);
        }
        asm volatile("cp.async.commit_group;\n");
    };

    issue(0, 0);

    for (int kt = 0; kt < nk; kt++) {
        asm volatile("cp.async.wait_group 0;\n");
        __syncthreads();
        if (kt + 1 < nk) issue(kt + 1, (kt + 1) & 1);

        const __half* As = smem + (kt & 1) * 2 * HSTAGE;
        const __half* Bs = As + HSTAGE;
        int mrow = wm * 64;
        int ncol = wn * 32;

#pragma unroll
        for (int ks = 0; ks < 2; ks++) {
            int k0 = ks << 4;
            uint32_t af[4][4];
#pragma unroll
            for (int mt = 0; mt < 4; mt++) {
                int r0 = mrow + mt * 16 + g;
                af[mt][0] = *(const uint32_t*)&As[r0 * HP + k0 + 2*c];
                af[mt][1] = *(const uint32_t*)&As[(r0 + 8) * HP + k0 + 2*c];
                af[mt][2] = *(const uint32_t*)&As[r0 * HP + k0 + 2*c + 8];
                af[mt][3] = *(const uint32_t*)&As[(r0 + 8) * HP + k0 + 2*c + 8];
            }
            uint32_t bf[4][2];
#pragma unroll
            for (int nt = 0; nt < 4; nt++) {
                int n0 = ncol + nt * 8 + g;
                bf[nt][0] = *(const uint32_t*)&Bs[n0 * HP + k0 + 2*c];
                bf[nt][1] = *(const uint32_t*)&Bs[n0 * HP + k0 + 2*c + 8];
            }
#pragma unroll
            for (int mt = 0; mt < 4; mt++)
#pragma unroll
                for (int nt = 0; nt < 4; nt++)
                    mma_f16(acc[mt][nt], af[mt][0], af[mt][1], af[mt][2], af[mt][3],
                            bf[nt][0], bf[nt][1]);
        }
        __syncthreads();
    }

    // epilogue
    float* Cf = (float*)Cout;
    __half* Ch = (__half*)Cout;
#pragma unroll
    for (int mt = 0; mt < 4; mt++) {
#pragma unroll
        for (int nt = 0; nt < 4; nt++) {
            int row = by * 128 + wm * 64 + mt * 16 + g;
            int col = bx * 128 + wn * 32 + nt * 8 + 2 * c;
#pragma unroll
            for (int half_ = 0; half_ < 2; half_++) {
                int rr = row + half_ * 8;
                float v0 = (acc[mt][nt][half_*2+0] + bias[col])     * alpha;
                float v1 = (acc[mt][nt][half_*2+1] + bias[col + 1]) * alpha;
                if (gelu) {
                    v0 = 0.5f * v0 * (1.0f + erff(v0 * 0.70710678118654752f));
                    v1 = 0.5f * v1 * (1.0f + erff(v1 * 0.70710678118654752f));
                }
                if (res) {
                    v0 += res[(size_t)rr * N + col];
                    v1 += res[(size_t)rr * N + col + 1];
                }
                if (out_half) {
                    __half2 o = __floats2half2_rn(v0, v1);
                    *(__half2*)&Ch[(size_t)rr * N + col] = o;
                } else {
                    float2 o = {v0, v1};
                    *(float2*)&Cf[(size_t)rr * N + col] = o;
                }
            }
        }
    }
}

// ------------------------- LayerNorm + window partition (fp16 out) ---------
__global__ void ln_part_kernel(const float* __restrict__ x, const float* __restrict__ g,
                               const float* __restrict__ b, __half* __restrict__ out,
                               int to_window)
{
    int warp = threadIdx.x >> 5, lane = threadIdx.x & 31;
    int p = blockIdx.x * 8 + warp;
    const float* row = x + (size_t)p * CDIM;
    float4 v0 = *(const float4*)(row + lane*4);
    float4 v1 = *(const float4*)(row + 128 + lane*4);
    float s  = v0.x+v0.y+v0.z+v0.w + v1.x+v1.y+v1.z+v1.w;
    float sq = v0.x*v0.x+v0.y*v0.y+v0.z*v0.z+v0.w*v0.w
             + v1.x*v1.x+v1.y*v1.y+v1.z*v1.z+v1.w*v1.w;
#pragma unroll
    for (int o = 16; o; o >>= 1) {
        s  += __shfl_xor_sync(0xffffffffu, s,  o);
        sq += __shfl_xor_sync(0xffffffffu, sq, o);
    }
    float mean = s * (1.0f/CDIM);
    float var  = sq * (1.0f/CDIM) - mean*mean;
    float rstd = rsqrtf(var + 1e-5f);
    int r = to_window ? win_row(p) : p;
    __half* orow = out + (size_t)r * CDIM;
    int c0 = lane*4;
    __half2 h0 = __floats2half2_rn((v0.x-mean)*rstd*g[c0+0] + b[c0+0],
                                   (v0.y-mean)*rstd*g[c0+1] + b[c0+1]);
    __half2 h1 = __floats2half2_rn((v0.z-mean)*rstd*g[c0+2] + b[c0+2],
                                   (v0.w-mean)*rstd*g[c0+3] + b[c0+3]);
    __half2 h2 = __floats2half2_rn((v1.x-mean)*rstd*g[c0+128+0] + b[c0+128+0],
                                   (v1.y-mean)*rstd*g[c0+128+1] + b[c0+128+1]);
    __half2 h3 = __floats2half2_rn((v1.z-mean)*rstd*g[c0+128+2] + b[c0+128+2],
                                   (v1.w-mean)*rstd*g[c0+128+3] + b[c0+128+3]);
    *(__half2*)(orow + c0)           = h0;
    *(__half2*)(orow + c0 + 2)       = h1;
    *(__half2*)(orow + 128 + c0)     = h2;
    *(__half2*)(orow + 128 + c0 + 2) = h3;
}

// ------------------------- residual + LN2 (window-reverse) -----------------
__global__ void res_ln2_kernel(const float* __restrict__ proj, const float* __restrict__ sc,
                               const float* __restrict__ g, const float* __restrict__ b,
                               float* __restrict__ zt, __half* __restrict__ ln2)
{
    int warp = threadIdx.x >> 5, lane = threadIdx.x & 31;
    int p = blockIdx.x * 8 + warp;
    int r = win_row(p);
    const float* prow = proj + (size_t)r * CDIM;
    const float* srow = sc   + (size_t)p * CDIM;
    int c0 = lane*4;
    float4 a0 = *(const float4*)(prow + c0);
    float4 a1 = *(const float4*)(prow + 128 + c0);
    float4 s0 = *(const float4*)(srow + c0);
    float4 s1 = *(const float4*)(srow + 128 + c0);
    float4 v0 = {a0.x+s0.x, a0.y+s0.y, a0.z+s0.z, a0.w+s0.w};
    float4 v1 = {a1.x+s1.x, a1.y+s1.y, a1.z+s1.z, a1.w+s1.w};
    *(float4*)(zt + (size_t)p*CDIM + c0)       = v0;
    *(float4*)(zt + (size_t)p*CDIM + 128 + c0) = v1;
    float s  = v0.x+v0.y+v0.z+v0.w + v1.x+v1.y+v1.z+v1.w;
    float sq = v0.x*v0.x+v0.y*v0.y+v0.z*v0.z+v0.w*v0.w
             + v1.x*v1.x+v1.y*v1.y+v1.z*v1.z+v1.w*v1.w;
#pragma unroll
    for (int o = 16; o; o >>= 1) {
        s  += __shfl_xor_sync(0xffffffffu, s,  o);
        sq += __shfl_xor_sync(0xffffffffu, sq, o);
    }
    float mean = s * (1.0f/CDIM);
    float var  = sq * (1.0f/CDIM) - mean*mean;
    float rstd = rsqrtf(var + 1e-5f);
    __half* orow = ln2 + (size_t)p * CDIM;
    __half2 h0 = __floats2half2_rn((v0.x-mean)*rstd*g[c0+0]+b[c0+0],
                                   (v0.y-mean)*rstd*g[c0+1]+b[c0+1]);
    __half2 h1 = __floats2half2_rn((v0.z-mean)*rstd*g[c0+2]+b[c0+2],
                                   (v0.w-mean)*rstd*g[c0+3]+b[c0+3]);
    __half2 h2 = __floats2half2_rn((v1.x-mean)*rstd*g[c0+128+0]+b[c0+128+0],
                                   (v1.y-mean)*rstd*g[c0+128+1]+b[c0+128+1]);
    __half2 h3 = __floats2half2_rn((v1.z-mean)*rstd*g[c0+128+2]+b[c0+128+2],
                                   (v1.w-mean)*rstd*g[c0+128+3]+b[c0+128+3]);
    *(__half2*)(orow + c0)           = h0;
    *(__half2*)(orow + c0 + 2)       = h1;
    *(__half2*)(orow + 128 + c0)     = h2;
    *(__half2*)(orow + 128 + c0 + 2) = h3;
}

// ------------------------- windowed attention (fp16 out) -------------------
__global__ __launch_bounds__(128)
void attn_kernel(const float* __restrict__ q, const float* __restrict__ k,
                 const float* __restrict__ v, const float* __restrict__ rpb,
                 __half* __restrict__ out)
{
    __shared__ float qs[64][33];
    __shared__ float ks[64][33];
    __shared__ float vs[64][33];
    __shared__ float S [64][65];
    int win = blockIdx.x, h = blockIdx.y;
    int tid = threadIdx.x;
    size_t base = ((size_t)win * 64) * CDIM + h * HD;

    for (int idx = tid; idx < 64*HD; idx += 128) {
        int n = idx >> 5, d = idx & 31;
        qs[n][d] = q[base + (size_t)n*CDIM + d];
        ks[n][d] = k[base + (size_t)n*CDIM + d];
        vs[n][d] = v[base + (size_t)n*CDIM + d];
    }
    __syncthreads();

    for (int idx = tid; idx < 64*64; idx += 128) {
        int n = idx >> 6, m = idx & 63;
        float s = 0.f;
#pragma unroll
        for (int d = 0; d < HD; d++) s = fmaf(qs[n][d], ks[m][d], s);
        int di = (n >> 3) - (m >> 3) + 7;
        int dj = (n & 7)  - (m & 7)  + 7;
        s += rpb[(di*15 + dj)*NHEAD + h];
        S[n][m] = s;
    }
    __syncthreads();

    if (tid < 64) {
        int n = tid;
        float mx = -1e30f;
#pragma unroll
        for (int m = 0; m < 64; m++) mx = fmaxf(mx, S[n][m]);
        float sum = 0.f;
#pragma unroll
        for (int m = 0; m < 64; m++) { float e = expf(S[n][m] - mx); S[n][m] = e; sum += e; }
        float inv = 1.0f / sum;
#pragma unroll
        for (int m = 0; m < 64; m++) S[n][m] *= inv;
    }
    __syncthreads();

    for (int idx = tid; idx < 64*HD; idx += 128) {
        int n = idx >> 5, d = idx & 31;
        float o = 0.f;
#pragma unroll
        for (int m = 0; m < 64; m++) o = fmaf(S[n][m], vs[m][d], o);
        out[base + (size_t)n*CDIM + d] = __float2half_rn(o);
    }
}

// ---------------------------------------------------------------------------
extern "C" void kernel_launch(void* const* d_in, const int* in_sizes, int n_in,
                              void* d_out, int out_size)
{
    const float* LH      = (const float*)d_in[0];
    const float* HL      = (const float*)d_in[1];
    const float* HH      = (const float*)d_in[2];
    const float* Spat    = (const float*)d_in[3];
    const float* w_hllh  = (const float*)d_in[4];
    const float* b_hllh  = (const float*)d_in[5];
    const float* w_hh    = (const float*)d_in[6];
    const float* b_hh    = (const float*)d_in[7];
    const float* w_spat  = (const float*)d_in[8];
    const float* b_spat  = (const float*)d_in[9];
    const float* ln1x_g  = (const float*)d_in[10];
    const float* ln1x_b  = (const float*)d_in[11];
    const float* ln1y_g  = (const float*)d_in[12];
    const float* ln1y_b  = (const float*)d_in[13];
    const float* qkv_w   = (const float*)d_in[14];
    const float* qkv_b   = (const float*)d_in[15];
    const float* qkv2_w  = (const float*)d_in[16];
    const float* qkv2_b  = (const float*)d_in[17];
    const float* qkv3_w  = (const float*)d_in[18];
    const float* qkv3_b  = (const float*)d_in[19];
    const float* proj_w  = (const float*)d_in[20];
    const float* proj_b  = (const float*)d_in[21];
    const float* rpb     = (const float*)d_in[22];
    const float* ln2_g   = (const float*)d_in[23];
    const float* ln2_b   = (const float*)d_in[24];
    const float* fc1_w   = (const float*)d_in[25];
    const float* fc1_b   = (const float*)d_in[26];
    const float* fc2_w   = (const float*)d_in[27];
    const float* fc2_b   = (const float*)d_in[28];
    float* out = (float*)d_out;

    __half *inx, *iny, *inz, *xn, *yn, *ao, *ln2h, *hbuf, *wbuf;
    float *x, *y, *shrt, *q, *k, *v, *po, *zt, *zt2;
    cudaGetSymbolAddress((void**)&inx,  g_inx);
    cudaGetSymbolAddress((void**)&iny,  g_iny);
    cudaGetSymbolAddress((void**)&inz,  g_inz);
    cudaGetSymbolAddress((void**)&x,    g_x);
    cudaGetSymbolAddress((void**)&y,    g_y);
    cudaGetSymbolAddress((void**)&xn,   g_xn);
    cudaGetSymbolAddress((void**)&yn,   g_yn);
    cudaGetSymbolAddress((void**)&shrt, g_short);
    cudaGetSymbolAddress((void**)&q,    g_q);
    cudaGetSymbolAddress((void**)&k,    g_k);
    cudaGetSymbolAddress((void**)&v,    g_v);
    cudaGetSymbolAddress((void**)&ao,   g_ao);
    cudaGetSymbolAddress((void**)&po,   g_po);
    cudaGetSymbolAddress((void**)&zt,   g_zt);
    cudaGetSymbolAddress((void**)&ln2h, g_ln2);
    cudaGetSymbolAddress((void**)&hbuf, g_h);
    cudaGetSymbolAddress((void**)&zt2,  g_zt2);
    cudaGetSymbolAddress((void**)&wbuf, g_w);

    dim3 tb(32, 8);
    const int M = P_TOT;
    const float qscale = 0.17677669529663688f;

    // weights -> fp16
    conv_w_kernel<<<(W_TOT + 255)/256, 256>>>(w_hllh, w_hh, w_spat, qkv_w, qkv2_w,
                                              qkv3_w, proj_w, fc1_w, fc2_w, wbuf);

    // pack NCHW -> row-major fp16
    pack_kernel<<<dim3(HW_/32, 2, B_), tb>>>(LH,   inx, 64, 128, 0);
    pack_kernel<<<dim3(HW_/32, 2, B_), tb>>>(HL,   inx, 64, 128, 64);
    pack_kernel<<<dim3(HW_/32, 2, B_), tb>>>(HH,   inz, 64, 64, 0);
    pack_kernel<<<dim3(HW_/32, 2, B_), tb>>>(Spat, iny, 64, 64, 0);

    // 1x1 convs (fp32 out)
    gemm_h<<<dim3(2, M/128), 256, GSMEM>>>(inx, wbuf+WO_HLLH, b_hllh, nullptr, x,    M, 256, 128, 1.f, 0, 0);
    gemm_h<<<dim3(2, M/128), 256, GSMEM>>>(inz, wbuf+WO_HH,   b_hh,   nullptr, shrt, M, 256, 64,  1.f, 0, 0);
    gemm_h<<<dim3(2, M/128), 256, GSMEM>>>(iny, wbuf+WO_SPAT, b_spat, nullptr, y,    M, 256, 64,  1.f, 0, 0);

    // LN + window partition (fp16 out)
    ln_part_kernel<<<M/8, 256>>>(x, ln1x_g, ln1x_b, xn, 1);
    ln_part_kernel<<<M/8, 256>>>(y, ln1y_g, ln1y_b, yn, 1);

    // q/k/v projections (fp32 out)
    gemm_h<<<dim3(2, M/128), 256, GSMEM>>>(xn, wbuf+WO_QKV,  qkv_b,  nullptr, q, M, 256, 256, qscale, 0, 0);
    gemm_h<<<dim3(2, M/128), 256, GSMEM>>>(yn, wbuf+WO_QKV2, qkv2_b, nullptr, k, M, 256, 256, 1.f, 0, 0);
    gemm_h<<<dim3(2, M/128), 256, GSMEM>>>(yn, wbuf+WO_QKV3, qkv3_b, nullptr, v, M, 256, 256, 1.f, 0, 0);

    // windowed attention (fp16 out)
    attn_kernel<<<dim3(2048, NHEAD), 128>>>(q, k, v, rpb, ao);

    // output projection (fp32 out)
    gemm_h<<<dim3(2, M/128), 256, GSMEM>>>(ao, wbuf+WO_PROJ, proj_b, nullptr, po, M, 256, 256, 1.f, 0, 0);

    // window reverse + residual + LN2 (ln2 fp16)
    res_ln2_kernel<<<M/8, 256>>>(po, shrt, ln2_g, ln2_b, zt, ln2h);

    // MLP (fc1 fp16 out + gelu, fc2 fp32 + residual)
    gemm_h<<<dim3(8, M/128), 256, GSMEM>>>(ln2h, wbuf+WO_FC1, fc1_b, nullptr, hbuf, M, HID, 256, 1.f, 1, 1);
    gemm_h<<<dim3(2, M/128), 256, GSMEM>>>(hbuf, wbuf+WO_FC2, fc2_b, zt,      zt2,  M, 256, HID, 1.f, 0, 0);

    // [P,C] -> NCHW
    unpack_kernel<<<dim3(HW_/32, 8, B_), tb>>>(zt2, out);
}

// round 6
// speedup vs baseline: 4.9723x; 1.3584x over previous
#include <cuda_runtime.h>
#include <cuda_fp16.h>
#include <math.h>
#include <stdint.h>

// ---------------------------------------------------------------------------
// WaveletSwinTransformerBlock — fp16 mma GEMMs + fp16 mma attention
// ---------------------------------------------------------------------------

#define B_     8
#define H_     128
#define W_     128
#define HW_    (H_*W_)           // 16384
#define P_TOT  (B_*HW_)          // 131072
#define CDIM   256
#define NHEAD  8
#define HD     32
#define HID    1024

// ------------------------- scratch buffers (static) ------------------------
__device__ __half g_inx[(size_t)P_TOT*128];
__device__ __half g_iny[(size_t)P_TOT*64];
__device__ __half g_inz[(size_t)P_TOT*64];
__device__ __half g_x    [(size_t)P_TOT*CDIM];
__device__ __half g_y    [(size_t)P_TOT*CDIM];
__device__ __half g_xn   [(size_t)P_TOT*CDIM];
__device__ __half g_yn   [(size_t)P_TOT*CDIM];
__device__ float  g_short[(size_t)P_TOT*CDIM];
__device__ __half g_q    [(size_t)P_TOT*CDIM];
__device__ __half g_k    [(size_t)P_TOT*CDIM];
__device__ __half g_v    [(size_t)P_TOT*CDIM];
__device__ __half g_ao   [(size_t)P_TOT*CDIM];
__device__ __half g_po   [(size_t)P_TOT*CDIM];
__device__ float  g_zt   [(size_t)P_TOT*CDIM];
__device__ __half g_ln2  [(size_t)P_TOT*CDIM];
__device__ __half g_h    [(size_t)P_TOT*HID];
__device__ float  g_zt2  [(size_t)P_TOT*CDIM];

// fp16 weights, concatenated
#define WO_HLLH 0
#define WO_HH   32768
#define WO_SPAT 49152
#define WO_QKV  65536
#define WO_QKV2 131072
#define WO_QKV3 196608
#define WO_PROJ 262144
#define WO_FC1  327680
#define WO_FC2  589824
#define W_TOT   851968
__device__ __half g_w[W_TOT];

__device__ __forceinline__ int win_row(int p) {
    int b  = p >> 14;
    int hw = p & 16383;
    int h  = hw >> 7, w = hw & 127;
    int win = (b << 8) | ((h >> 3) << 4) | (w >> 3);
    int tok = ((h & 7) << 3) | (w & 7);
    return (win << 6) | tok;
}

// ------------------------- weight conversion -------------------------------
__global__ void conv_w_kernel(const float* w0, const float* w1, const float* w2,
                              const float* w3, const float* w4, const float* w5,
                              const float* w6, const float* w7, const float* w8,
                              __half* dst)
{
    int i = blockIdx.x * 256 + threadIdx.x;
    if (i >= W_TOT) return;
    float v;
    if      (i < WO_HH)   v = w0[i - WO_HLLH];
    else if (i < WO_SPAT) v = w1[i - WO_HH];
    else if (i < WO_QKV)  v = w2[i - WO_SPAT];
    else if (i < WO_QKV2) v = w3[i - WO_QKV];
    else if (i < WO_QKV3) v = w4[i - WO_QKV2];
    else if (i < WO_PROJ) v = w5[i - WO_QKV3];
    else if (i < WO_FC1)  v = w6[i - WO_PROJ];
    else if (i < WO_FC2)  v = w7[i - WO_FC1];
    else                  v = w8[i - WO_FC2];
    dst[i] = __float2half_rn(v);
}

// ------------------------- pack: NCHW -> [P, Cin] fp16 ---------------------
__global__ void pack_kernel(const float* __restrict__ src, __half* __restrict__ dst,
                            int Cin, int rowStride, int colOff)
{
    __shared__ float s[32][33];
    int hw0 = blockIdx.x * 32;
    int c0  = blockIdx.y * 32;
    int b   = blockIdx.z;
    int tx = threadIdx.x, ty = threadIdx.y;
#pragma unroll
    for (int i = 0; i < 4; i++)
        s[ty + 8*i][tx] = src[((size_t)(b*Cin + c0 + ty + 8*i))*HW_ + hw0 + tx];
    __syncthreads();
#pragma unroll
    for (int i = 0; i < 4; i++)
        dst[(size_t)(b*HW_ + hw0 + ty + 8*i)*rowStride + colOff + c0 + tx] =
            __float2half_rn(s[tx][ty + 8*i]);
}

// ------------------------- unpack: [P, C] -> NCHW --------------------------
__global__ void unpack_kernel(const float* __restrict__ src, float* __restrict__ dst)
{
    __shared__ float s[32][33];
    int hw0 = blockIdx.x * 32;
    int c0  = blockIdx.y * 32;
    int b   = blockIdx.z;
    int tx = threadIdx.x, ty = threadIdx.y;
#pragma unroll
    for (int i = 0; i < 4; i++)
        s[ty + 8*i][tx] = src[(size_t)(b*HW_ + hw0 + ty + 8*i)*CDIM + c0 + tx];
    __syncthreads();
#pragma unroll
    for (int i = 0; i < 4; i++)
        dst[(size_t)(b*CDIM + c0 + ty + 8*i)*HW_ + hw0 + tx] = s[tx][ty + 8*i];
}

// ------------------------- fp16 tensor-core GEMM ---------------------------
#define HP 72
#define HSTAGE (128*HP)
#define GSMEM  (2 * 2 * HSTAGE * 2)  // 73728 bytes

__device__ __forceinline__ void mma_f16(float c[4], uint32_t a0, uint32_t a1,
                                        uint32_t a2, uint32_t a3,
                                        uint32_t b0, uint32_t b1)
{
    asm volatile(
        "mma.sync.aligned.m16n8k16.row.col.f32.f16.f16.f32 "
        "{%0,%1,%2,%3}, {%4,%5,%6,%7}, {%8,%9}, {%0,%1,%2,%3};\n"
        : "+f"(c[0]), "+f"(c[1]), "+f"(c[2]), "+f"(c[3])
        : "r"(a0), "r"(a1), "r"(a2), "r"(a3), "r"(b0), "r"(b1));
}

__device__ __forceinline__ void cp16(uint32_t dst_smem, const __half* src) {
    asm volatile("cp.async.cg.shared.global [%0], [%1], 16;\n"
                 :: "r"(dst_smem), "l"(src));
}

__global__ __launch_bounds__(256, 2)
void gemm_h(const __half* __restrict__ A, const __half* __restrict__ Wm,
            const float* __restrict__ bias, const float* __restrict__ res,
            void* __restrict__ Cout, int M, int N, int K, float alpha,
            int gelu, int out_half)
{
    extern __shared__ __half smem[];
    const uint32_t smem_base = (uint32_t)__cvta_generic_to_shared(smem);

    int bx = blockIdx.x, by = blockIdx.y;
    int tid  = threadIdx.x;
    int warp = tid >> 5, lane = tid & 31;
    int wm = warp >> 2;
    int wn = warp & 3;
    int g  = lane >> 2, c = lane & 3;

    const __half* Ab = A  + (size_t)by * 128 * K;
    const __half* Wb = Wm + (size_t)bx * 128 * K;

    float acc[4][4][4];
#pragma unroll
    for (int i = 0; i < 4; i++)
#pragma unroll
        for (int j = 0; j < 4; j++)
#pragma unroll
            for (int r = 0; r < 4; r++) acc[i][j][r] = 0.f;

    const int nk = K >> 6;

    auto issue = [&](int kt, int buf) {
        int k0 = kt << 6;
        uint32_t sa = smem_base + (uint32_t)(buf * 2 * HSTAGE) * 2u;
        uint32_t sb = sa + (uint32_t)HSTAGE * 2u;
#pragma unroll
        for (int i = 0; i < 4; i++) {
            int ch = tid + (i << 8);
            int row = ch >> 3;
            int c8  = (ch & 7) << 3;
            cp16(sa + (uint32_t)(row * HP + c8) * 2u, Ab + (size_t)row * K + k0 + c8);
            cp16(sb + (uint32_t)(row * HP + c8) * 2u, Wb + (size_t)row * K + k0 + c8);
        }
        asm volatile("cp.async.commit_group;\n");
    };

    issue(0, 0);

    for (int kt = 0; kt < nk; kt++) {
        asm volatile("cp.async.wait_group 0;\n");
        __syncthreads();
        if (kt + 1 < nk) issue(kt + 1, (kt + 1) & 1);

        const __half* As = smem + (kt & 1) * 2 * HSTAGE;
        const __half* Bs = As + HSTAGE;
        int mrow = wm * 64;
        int ncol = wn * 32;

#pragma unroll
        for (int ks = 0; ks < 4; ks++) {
            int k0 = ks << 4;
            uint32_t af[4][4];
#pragma unroll
            for (int mt = 0; mt < 4; mt++) {
                int r0 = mrow + mt * 16 + g;
                af[mt][0] = *(const uint32_t*)&As[r0 * HP + k0 + 2*c];
                af[mt][1] = *(const uint32_t*)&As[(r0 + 8) * HP + k0 + 2*c];
                af[mt][2] = *(const uint32_t*)&As[r0 * HP + k0 + 2*c + 8];
                af[mt][3] = *(const uint32_t*)&As[(r0 + 8) * HP + k0 + 2*c + 8];
            }
            uint32_t bf[4][2];
#pragma unroll
            for (int nt = 0; nt < 4; nt++) {
                int n0 = ncol + nt * 8 + g;
                bf[nt][0] = *(const uint32_t*)&Bs[n0 * HP + k0 + 2*c];
                bf[nt][1] = *(const uint32_t*)&Bs[n0 * HP + k0 + 2*c + 8];
            }
#pragma unroll
            for (int mt = 0; mt < 4; mt++)
#pragma unroll
                for (int nt = 0; nt < 4; nt++)
                    mma_f16(acc[mt][nt], af[mt][0], af[mt][1], af[mt][2], af[mt][3],
                            bf[nt][0], bf[nt][1]);
        }
        __syncthreads();
    }

    float* Cf = (float*)Cout;
    __half* Ch = (__half*)Cout;
#pragma unroll
    for (int mt = 0; mt < 4; mt++) {
#pragma unroll
        for (int nt = 0; nt < 4; nt++) {
            int row = by * 128 + wm * 64 + mt * 16 + g;
            int col = bx * 128 + wn * 32 + nt * 8 + 2 * c;
#pragma unroll
            for (int half_ = 0; half_ < 2; half_++) {
                int rr = row + half_ * 8;
                float v0 = (acc[mt][nt][half_*2+0] + bias[col])     * alpha;
                float v1 = (acc[mt][nt][half_*2+1] + bias[col + 1]) * alpha;
                if (gelu) {
                    v0 = 0.5f * v0 * (1.0f + erff(v0 * 0.70710678118654752f));
                    v1 = 0.5f * v1 * (1.0f + erff(v1 * 0.70710678118654752f));
                }
                if (res) {
                    v0 += res[(size_t)rr * N + col];
                    v1 += res[(size_t)rr * N + col + 1];
                }
                if (out_half) {
                    __half2 o = __floats2half2_rn(v0, v1);
                    *(__half2*)&Ch[(size_t)rr * N + col] = o;
                } else {
                    float2 o = {v0, v1};
                    *(float2*)&Cf[(size_t)rr * N + col] = o;
                }
            }
        }
    }
}

// ------------------------- LayerNorm + window partition (fp16 in/out) ------
__global__ void ln_part_kernel(const __half* __restrict__ x, const float* __restrict__ g,
                               const float* __restrict__ b, __half* __restrict__ out,
                               int to_window)
{
    int warp = threadIdx.x >> 5, lane = threadIdx.x & 31;
    int p = blockIdx.x * 8 + warp;
    const __half* row = x + (size_t)p * CDIM;
    int c0 = lane * 8;
    uint4 w = *(const uint4*)(row + c0);
    __half2* hw = (__half2*)&w;
    float v[8];
#pragma unroll
    for (int i = 0; i < 4; i++) {
        float2 f = __half22float2(hw[i]);
        v[2*i] = f.x; v[2*i+1] = f.y;
    }
    float s = 0.f, sq = 0.f;
#pragma unroll
    for (int i = 0; i < 8; i++) { s += v[i]; sq += v[i]*v[i]; }
#pragma unroll
    for (int o = 16; o; o >>= 1) {
        s  += __shfl_xor_sync(0xffffffffu, s,  o);
        sq += __shfl_xor_sync(0xffffffffu, sq, o);
    }
    float mean = s * (1.0f/CDIM);
    float var  = sq * (1.0f/CDIM) - mean*mean;
    float rstd = rsqrtf(var + 1e-5f);
    int r = to_window ? win_row(p) : p;
    uint4 o4;
    __half2* ho = (__half2*)&o4;
#pragma unroll
    for (int i = 0; i < 4; i++)
        ho[i] = __floats2half2_rn((v[2*i]  -mean)*rstd*g[c0+2*i]   + b[c0+2*i],
                                  (v[2*i+1]-mean)*rstd*g[c0+2*i+1] + b[c0+2*i+1]);
    *(uint4*)(out + (size_t)r * CDIM + c0) = o4;
}

// ------------------------- residual + LN2 (window-reverse) -----------------
__global__ void res_ln2_kernel(const __half* __restrict__ proj, const float* __restrict__ sc,
                               const float* __restrict__ g, const float* __restrict__ b,
                               float* __restrict__ zt, __half* __restrict__ ln2)
{
    int warp = threadIdx.x >> 5, lane = threadIdx.x & 31;
    int p = blockIdx.x * 8 + warp;
    int r = win_row(p);
    int c0 = lane * 8;
    uint4 wp = *(const uint4*)(proj + (size_t)r * CDIM + c0);
    __half2* hp2 = (__half2*)&wp;
    float4 s0 = *(const float4*)(sc + (size_t)p*CDIM + c0);
    float4 s1 = *(const float4*)(sc + (size_t)p*CDIM + c0 + 4);
    float sa[8] = {s0.x,s0.y,s0.z,s0.w, s1.x,s1.y,s1.z,s1.w};
    float v[8];
#pragma unroll
    for (int i = 0; i < 4; i++) {
        float2 f = __half22float2(hp2[i]);
        v[2*i] = f.x + sa[2*i]; v[2*i+1] = f.y + sa[2*i+1];
    }
    float4 z0 = {v[0],v[1],v[2],v[3]};
    float4 z1 = {v[4],v[5],v[6],v[7]};
    *(float4*)(zt + (size_t)p*CDIM + c0)     = z0;
    *(float4*)(zt + (size_t)p*CDIM + c0 + 4) = z1;
    float s = 0.f, sq = 0.f;
#pragma unroll
    for (int i = 0; i < 8; i++) { s += v[i]; sq += v[i]*v[i]; }
#pragma unroll
    for (int o = 16; o; o >>= 1) {
        s  += __shfl_xor_sync(0xffffffffu, s,  o);
        sq += __shfl_xor_sync(0xffffffffu, sq, o);
    }
    float mean = s * (1.0f/CDIM);
    float var  = sq * (1.0f/CDIM) - mean*mean;
    float rstd = rsqrtf(var + 1e-5f);
    uint4 o4;
    __half2* ho = (__half2*)&o4;
#pragma unroll
    for (int i = 0; i < 4; i++)
        ho[i] = __floats2half2_rn((v[2*i]  -mean)*rstd*g[c0+2*i]   + b[c0+2*i],
                                  (v[2*i+1]-mean)*rstd*g[c0+2*i+1] + b[c0+2*i+1]);
    *(uint4*)(ln2 + (size_t)p * CDIM + c0) = o4;
}

// ------------------------- mma windowed attention --------------------------
__global__ __launch_bounds__(256)
void attn_kernel(const __half* __restrict__ q, const __half* __restrict__ k,
                 const __half* __restrict__ v, const float* __restrict__ rpb,
                 __half* __restrict__ out)
{
    __shared__ __half qs [64*72];
    __shared__ __half ks_[64*72];
    __shared__ __half vst[2*32*72];
    __shared__ float  rpbs[1800];
    int win = blockIdx.x, hp = blockIdx.y;
    int tid = threadIdx.x;
    size_t base = (size_t)win * 64 * CDIM + hp * 64;

    for (int i = tid; i < 2048; i += 256) {
        int n = i >> 5, j = i & 31;
        *(uint32_t*)(qs  + n*72 + 2*j) = *(const uint32_t*)(q + base + (size_t)n*CDIM + 2*j);
        *(uint32_t*)(ks_ + n*72 + 2*j) = *(const uint32_t*)(k + base + (size_t)n*CDIM + 2*j);
        __half2 wv = *(const __half2*)(v + base + (size_t)n*CDIM + 2*j);
        int dl = 2*j, hl = dl >> 5, dd = dl & 31;
        vst[hl*2304 + dd*72 + n]     = __low2half(wv);
        vst[hl*2304 + (dd+1)*72 + n] = __high2half(wv);
    }
    for (int i = tid; i < 1800; i += 256) rpbs[i] = rpb[i];
    __syncthreads();

    int warp = tid >> 5, lane = tid & 31;
    int hl = warp >> 2, mq = warp & 3;
    int h  = hp * 2 + hl;
    int g  = lane >> 2, c = lane & 3;

    float sacc[8][4];
#pragma unroll
    for (int nt = 0; nt < 8; nt++)
#pragma unroll
        for (int r = 0; r < 4; r++) sacc[nt][r] = 0.f;

#pragma unroll
    for (int ks = 0; ks < 2; ks++) {
        int kc = hl*32 + ks*16 + 2*c;
        int r0 = mq*16 + g;
        uint32_t a0 = *(const uint32_t*)&qs[r0*72 + kc];
        uint32_t a1 = *(const uint32_t*)&qs[(r0+8)*72 + kc];
        uint32_t a2 = *(const uint32_t*)&qs[r0*72 + kc + 8];
        uint32_t a3 = *(const uint32_t*)&qs[(r0+8)*72 + kc + 8];
#pragma unroll
        for (int nt = 0; nt < 8; nt++) {
            int n0 = nt*8 + g;
            uint32_t b0 = *(const uint32_t*)&ks_[n0*72 + kc];
            uint32_t b1 = *(const uint32_t*)&ks_[n0*72 + kc + 8];
            mma_f16(sacc[nt], a0, a1, a2, a3, b0, b1);
        }
    }

    int dj0 = g - 2*c + 7, dj1 = dj0 - 1;
#pragma unroll
    for (int nt = 0; nt < 8; nt++) {
        int di0 = mq*2 - nt + 7, di1 = di0 + 1;
        sacc[nt][0] += rpbs[(di0*15 + dj0)*NHEAD + h];
        sacc[nt][1] += rpbs[(di0*15 + dj1)*NHEAD + h];
        sacc[nt][2] += rpbs[(di1*15 + dj0)*NHEAD + h];
        sacc[nt][3] += rpbs[(di1*15 + dj1)*NHEAD + h];
    }

    float mxA = -1e30f, mxB = -1e30f;
#pragma unroll
    for (int nt = 0; nt < 8; nt++) {
        mxA = fmaxf(mxA, fmaxf(sacc[nt][0], sacc[nt][1]));
        mxB = fmaxf(mxB, fmaxf(sacc[nt][2], sacc[nt][3]));
    }
#pragma unroll
    for (int o = 1; o <= 2; o <<= 1) {
        mxA = fmaxf(mxA, __shfl_xor_sync(0xffffffffu, mxA, o));
        mxB = fmaxf(mxB, __shfl_xor_sync(0xffffffffu, mxB, o));
    }
    float smA = 0.f, smB = 0.f;
#pragma unroll
    for (int nt = 0; nt < 8; nt++) {
        sacc[nt][0] = expf(sacc[nt][0] - mxA); smA += sacc[nt][0];
        sacc[nt][1] = expf(sacc[nt][1] - mxA); smA += sacc[nt][1];
        sacc[nt][2] = expf(sacc[nt][2] - mxB); smB += sacc[nt][2];
        sacc[nt][3] = expf(sacc[nt][3] - mxB); smB += sacc[nt][3];
    }
#pragma unroll
    for (int o = 1; o <= 2; o <<= 1) {
        smA += __shfl_xor_sync(0xffffffffu, smA, o);
        smB += __shfl_xor_sync(0xffffffffu, smB, o);
    }
    float ivA = 1.0f / smA, ivB = 1.0f / smB;

    uint32_t pf[4][4];
#pragma unroll
    for (int kt = 0; kt < 4; kt++) {
        __half2 t;
        t = __floats2half2_rn(sacc[2*kt][0]*ivA,   sacc[2*kt][1]*ivA);   pf[kt][0] = *(uint32_t*)&t;
        t = __floats2half2_rn(sacc[2*kt][2]*ivB,   sacc[2*kt][3]*ivB);   pf[kt][1] = *(uint32_t*)&t;
        t = __floats2half2_rn(sacc[2*kt+1][0]*ivA, sacc[2*kt+1][1]*ivA); pf[kt][2] = *(uint32_t*)&t;
        t = __floats2half2_rn(sacc[2*kt+1][2]*ivB, sacc[2*kt+1][3]*ivB); pf[kt][3] = *(uint32_t*)&t;
    }

    float oacc[4][4];
#pragma unroll
    for (int nt = 0; nt < 4; nt++)
#pragma unroll
        for (int r = 0; r < 4; r++) oacc[nt][r] = 0.f;
    const __half* vh = vst + hl*2304;
#pragma unroll
    for (int kt = 0; kt < 4; kt++) {
#pragma unroll
        for (int nt = 0; nt < 4; nt++) {
            int n0 = nt*8 + g;
            uint32_t b0 = *(const uint32_t*)&vh[n0*72 + kt*16 + 2*c];
            uint32_t b1 = *(const uint32_t*)&vh[n0*72 + kt*16 + 2*c + 8];
            mma_f16(oacc[nt], pf[kt][0], pf[kt][1], pf[kt][2], pf[kt][3], b0, b1);
        }
    }

    __half* orow = out + (size_t)(win*64 + mq*16 + g) * CDIM + h*HD;
#pragma unroll
    for (int nt = 0; nt < 4; nt++) {
        __half2 o0 = __floats2half2_rn(oacc[nt][0], oacc[nt][1]);
        __half2 o1 = __floats2half2_rn(oacc[nt][2], oacc[nt][3]);
        *(__half2*)(orow + nt*8 + 2*c)          = o0;
        *(__half2*)(orow + 8*CDIM + nt*8 + 2*c) = o1;
    }
}

// ---------------------------------------------------------------------------
extern "C" void kernel_launch(void* const* d_in, const int* in_sizes, int n_in,
                              void* d_out, int out_size)
{
    const float* LH      = (const float*)d_in[0];
    const float* HL      = (const float*)d_in[1];
    const float* HH      = (const float*)d_in[2];
    const float* Spat    = (const float*)d_in[3];
    const float* w_hllh  = (const float*)d_in[4];
    const float* b_hllh  = (const float*)d_in[5];
    const float* w_hh    = (const float*)d_in[6];
    const float* b_hh    = (const float*)d_in[7];
    const float* w_spat  = (const float*)d_in[8];
    const float* b_spat  = (const float*)d_in[9];
    const float* ln1x_g  = (const float*)d_in[10];
    const float* ln1x_b  = (const float*)d_in[11];
    const float* ln1y_g  = (const float*)d_in[12];
    const float* ln1y_b  = (const float*)d_in[13];
    const float* qkv_w   = (const float*)d_in[14];
    const float* qkv_b   = (const float*)d_in[15];
    const float* qkv2_w  = (const float*)d_in[16];
    const float* qkv2_b  = (const float*)d_in[17];
    const float* qkv3_w  = (const float*)d_in[18];
    const float* qkv3_b  = (const float*)d_in[19];
    const float* proj_w  = (const float*)d_in[20];
    const float* proj_b  = (const float*)d_in[21];
    const float* rpb     = (const float*)d_in[22];
    const float* ln2_g   = (const float*)d_in[23];
    const float* ln2_b   = (const float*)d_in[24];
    const float* fc1_w   = (const float*)d_in[25];
    const float* fc1_b   = (const float*)d_in[26];
    const float* fc2_w   = (const float*)d_in[27];
    const float* fc2_b   = (const float*)d_in[28];
    float* out = (float*)d_out;

    __half *inx, *iny, *inz, *x, *y, *xn, *yn, *q, *k, *v, *ao, *po, *ln2h, *hbuf, *wbuf;
    float *shrt, *zt, *zt2;
    cudaGetSymbolAddress((void**)&inx,  g_inx);
    cudaGetSymbolAddress((void**)&iny,  g_iny);
    cudaGetSymbolAddress((void**)&inz,  g_inz);
    cudaGetSymbolAddress((void**)&x,    g_x);
    cudaGetSymbolAddress((void**)&y,    g_y);
    cudaGetSymbolAddress((void**)&xn,   g_xn);
    cudaGetSymbolAddress((void**)&yn,   g_yn);
    cudaGetSymbolAddress((void**)&shrt, g_short);
    cudaGetSymbolAddress((void**)&q,    g_q);
    cudaGetSymbolAddress((void**)&k,    g_k);
    cudaGetSymbolAddress((void**)&v,    g_v);
    cudaGetSymbolAddress((void**)&ao,   g_ao);
    cudaGetSymbolAddress((void**)&po,   g_po);
    cudaGetSymbolAddress((void**)&zt,   g_zt);
    cudaGetSymbolAddress((void**)&ln2h, g_ln2);
    cudaGetSymbolAddress((void**)&hbuf, g_h);
    cudaGetSymbolAddress((void**)&zt2,  g_zt2);
    cudaGetSymbolAddress((void**)&wbuf, g_w);

    static int smem_set = 0;
    if (!smem_set) {
        cudaFuncSetAttribute(gemm_h, cudaFuncAttributeMaxDynamicSharedMemorySize, GSMEM);
        smem_set = 1;
    }

    dim3 tb(32, 8);
    const int M = P_TOT;
    const float qscale = 0.17677669529663688f;

    conv_w_kernel<<<(W_TOT + 255)/256, 256>>>(w_hllh, w_hh, w_spat, qkv_w, qkv2_w,
                                              qkv3_w, proj_w, fc1_w, fc2_w, wbuf);

    pack_kernel<<<dim3(HW_/32, 2, B_), tb>>>(LH,   inx, 64, 128, 0);
    pack_kernel<<<dim3(HW_/32, 2, B_), tb>>>(HL,   inx, 64, 128, 64);
    pack_kernel<<<dim3(HW_/32, 2, B_), tb>>>(HH,   inz, 64, 64, 0);
    pack_kernel<<<dim3(HW_/32, 2, B_), tb>>>(Spat, iny, 64, 64, 0);

    gemm_h<<<dim3(2, M/128), 256, GSMEM>>>(inx, wbuf+WO_HLLH, b_hllh, nullptr, x,    M, 256, 128, 1.f, 0, 1);
    gemm_h<<<dim3(2, M/128), 256, GSMEM>>>(inz, wbuf+WO_HH,   b_hh,   nullptr, shrt, M, 256, 64,  1.f, 0, 0);
    gemm_h<<<dim3(2, M/128), 256, GSMEM>>>(iny, wbuf+WO_SPAT, b_spat, nullptr, y,    M, 256, 64,  1.f, 0, 1);

    ln_part_kernel<<<M/8, 256>>>(x, ln1x_g, ln1x_b, xn, 1);
    ln_part_kernel<<<M/8, 256>>>(y, ln1y_g, ln1y_b, yn, 1);

    gemm_h<<<dim3(2, M/128), 256, GSMEM>>>(xn, wbuf+WO_QKV,  qkv_b,  nullptr, q, M, 256, 256, qscale, 0, 1);
    gemm_h<<<dim3(2, M/128), 256, GSMEM>>>(yn, wbuf+WO_QKV2, qkv2_b, nullptr, k, M, 256, 256, 1.f, 0, 1);
    gemm_h<<<dim3(2, M/128), 256, GSMEM>>>(yn, wbuf+WO_QKV3, qkv3_b, nullptr, v, M, 256, 256, 1.f, 0, 1);

    attn_kernel<<<dim3(2048, NHEAD/2), 256>>>(q, k, v, rpb, ao);

    gemm_h<<<dim3(2, M/128), 256, GSMEM>>>(ao, wbuf+WO_PROJ, proj_b, nullptr, po, M, 256, 256, 1.f, 0, 1);

    res_ln2_kernel<<<M/8, 256>>>(po, shrt, ln2_g, ln2_b, zt, ln2h);

    gemm_h<<<dim3(8, M/128), 256, GSMEM>>>(ln2h, wbuf+WO_FC1, fc1_b, nullptr, hbuf, M, HID, 256, 1.f, 1, 1);
    gemm_h<<<dim3(2, M/128), 256, GSMEM>>>(hbuf, wbuf+WO_FC2, fc2_b, zt,      zt2,  M, 256, HID, 1.f, 0, 0);

    unpack_kernel<<<dim3(HW_/32, 8, B_), tb>>>(zt2, out);
}